// round 13
// baseline (speedup 1.0000x reference)
#include <cuda_runtime.h>
#include <cuda_fp16.h>
#include <cstdint>
#include <math.h>

#define SEQ 3072
#define DIM 1024
#define NHEAD 4
#define DHEAD 256
#define NLAYER 4
#define LN_EPS 1e-5f
typedef __half f16;

// ======================= scratch (static device arrays) =======================
__device__ float g_h[SEQ * DIM];
__device__ float g_split[2 * SEQ * DIM];                             // split-K partials

__device__ f16 g_h_hi[SEQ * DIM];
__device__ f16 g_qkvh[3 * SEQ * DIM];                                // [qkv][head][t][e]
__device__ f16 g_vht[SEQ * DIM];                                     // [head][e][t]
__device__ f16 g_ctx[SEQ * DIM];                                     // [t][head*DHEAD+e]
__device__ f16 g_f1[SEQ * 2 * DIM];
__device__ f16 g_at[(size_t)NHEAD * SEQ * SEQ];                      // scores/attn

// weights (fp16 hi; wht also keeps lo for the f32-exact bias fold)
__device__ f16 g_wsplit[3 * NLAYER * DIM * DIM];                     // [qkv][l][in][out]
__device__ f16 g_wpt[3 * NLAYER * NHEAD * DHEAD * DIM];              // W'^T [qkv][l][a][e][in]
__device__ f16 g_wot[NLAYER * DIM * DIM];
__device__ f16 g_wht_hi[NLAYER * NHEAD * DHEAD * DIM], g_wht_lo[NLAYER * NHEAD * DHEAD * DIM];
__device__ f16 g_w1t[NLAYER * DIM * 2 * DIM];
__device__ f16 g_w2t[NLAYER * 2 * DIM * DIM];
__device__ float g_bprime[NLAYER * 3 * NHEAD * DHEAD];               // [l][qkv][a][e]

// ======================= helpers =======================
__device__ __forceinline__ uint32_t s2u(const void* p) {
    uint32_t a;
    asm("{ .reg .u64 t; cvta.to.shared.u64 t, %1; cvt.u32.u64 %0, t; }" : "=r"(a) : "l"(p));
    return a;
}
__device__ __forceinline__ void split2(float x, f16& h, f16& l) {
    h = __float2half_rn(x);
    l = __float2half_rn(x - __half2float(h));
}
__device__ __forceinline__ void cp16(uint32_t dst, const void* src) {
    asm volatile("cp.async.cg.shared.global [%0], [%1], 16;" :: "r"(dst), "l"(src) : "memory");
}
#define CP_COMMIT() asm volatile("cp.async.commit_group;" ::: "memory")
#define CP_WAIT(n)  asm volatile("cp.async.wait_group %0;" :: "n"(n) : "memory")

__device__ __forceinline__ void ldm_x4(uint32_t* r, uint32_t addr) {
    asm volatile("ldmatrix.sync.aligned.m8n8.x4.shared.b16 {%0,%1,%2,%3}, [%4];"
                 : "=r"(r[0]), "=r"(r[1]), "=r"(r[2]), "=r"(r[3]) : "r"(addr));
}
__device__ __forceinline__ void mma_f16(float* c, const uint32_t* a, const uint32_t* b) {
    asm volatile(
        "mma.sync.aligned.m16n8k16.row.col.f32.f16.f16.f32 "
        "{%0,%1,%2,%3}, {%4,%5,%6,%7}, {%8,%9}, {%0,%1,%2,%3};"
        : "+f"(c[0]), "+f"(c[1]), "+f"(c[2]), "+f"(c[3])
        : "r"(a[0]), "r"(a[1]), "r"(a[2]), "r"(a[3]), "r"(b[0]), "r"(b[1]));
}

// ======================= fp16 mma.sync GEMM =======================
// C[m][n] = alpha * sum_k A[m][k]*B[n][k] + bias[n]   (A, B fp16; f32 accum)
// Tile 128x128, BK=64, 3-stage cp.async (32KB/stage: A 16K | B 16K), SW128,
// 2 CTAs/SM (2 x 96KB smem).
// Optional split-K: grid.z = batch*kSplit; partials Cpart[(zs*nzb+zb)*M*Npart + ...].
#define GSMEM_BYTES 98304
#define STAGE_BYTES 32768u

__global__ void __launch_bounds__(256, 2)
mma_gemm(const f16* __restrict__ A, int lda, long sAo, long sAi,
         const f16* __restrict__ B, int ldb, long sBo, long sBi,
         const float* __restrict__ bias, long sBias, int nB,
         float* __restrict__ C, f16* __restrict__ Chi,
         int ldc, long sC, int K, float alpha, int relu,
         int kSplit, float* __restrict__ Cpart)
{
    extern __shared__ char sm[];
    const uint32_t sb = s2u(sm);
    const int tid = threadIdx.x;
    const int wid = tid >> 5;
    const int lane = tid & 31;
    const int wm = wid >> 2;
    const int wn = wid & 3;
    int zb = blockIdx.z;
    int zs = 0;
    if (kSplit > 1) { zs = zb % kSplit; zb /= kSplit; }
    const int zo = zb / nB;
    const int zi = zb - zo * nB;
    const long row0 = (long)blockIdx.y * 128;
    const long col0 = (long)blockIdx.x * 128;

    const int Ksub = K / kSplit;
    const long koff = (long)zs * Ksub;

    A += zo * sAo + zi * sAi + koff;
    B += zo * sBo + zi * sBi + koff;

    const int nch = Ksub >> 6;

    auto load_chunk = [&](int ch, int stage) {
        const long k0 = (long)ch << 6;
#pragma unroll
        for (int i = 0; i < 8; i++) {
            const int u = tid + (i << 8);
            const int t = u >> 10;          // 0=A 1=B
            const int q = u & 1023;         // row*8 + seg
            const long r = q >> 3;
            const int sg = (q & 7) << 3;
            const f16* p = (t == 0) ? (A + (row0 + r) * lda) : (B + (col0 + r) * ldb);
            uint32_t off = (uint32_t)(q << 4);
            off ^= (off >> 3) & 0x70;
            cp16(sb + (uint32_t)stage * STAGE_BYTES + (uint32_t)t * 16384u + off, p + k0 + sg);
        }
        CP_COMMIT();
    };

    float acc[4][4][4];
#pragma unroll
    for (int a = 0; a < 4; a++)
#pragma unroll
        for (int b = 0; b < 4; b++)
#pragma unroll
            for (int c = 0; c < 4; c++) acc[a][b][c] = 0.0f;

    load_chunk(0, 0);
    load_chunk(1, 1);

    for (int ch = 0; ch < nch; ch++) {
        if (ch + 2 < nch) {
            load_chunk(ch + 2, (ch + 2) % 3);
            CP_WAIT(2);
        } else {
            CP_WAIT(0);
        }
        __syncthreads();

        const uint32_t stg = sb + (uint32_t)(ch % 3) * STAGE_BYTES;

#pragma unroll
        for (int ks = 0; ks < 4; ks++) {
            uint32_t ah[4][4], bh[2][4];
#pragma unroll
            for (int mt = 0; mt < 4; mt++) {
                const int row = wm * 64 + mt * 16 + (lane & 15);
                const int colb = ks * 32 + ((lane >> 4) << 4);
                uint32_t off = (uint32_t)(row * 128 + colb);
                off ^= (off >> 3) & 0x70;
                ldm_x4(ah[mt], stg + off);
            }
#pragma unroll
            for (int np = 0; np < 2; np++) {
                const int row = wn * 32 + np * 16 + (lane & 7) + ((lane >> 4) << 3);
                const int colb = ks * 32 + (((lane >> 3) & 1) << 4);
                uint32_t off = (uint32_t)(row * 128 + colb);
                off ^= (off >> 3) & 0x70;
                ldm_x4(bh[np], stg + 16384u + off);
            }
#pragma unroll
            for (int mt = 0; mt < 4; mt++)
#pragma unroll
                for (int nt = 0; nt < 4; nt++) {
                    const uint32_t* bhp = &bh[nt >> 1][(nt & 1) * 2];
                    mma_f16(acc[mt][nt], ah[mt], bhp);
                }
        }
        __syncthreads();
    }

    // -------- epilogue --------
    if (kSplit > 1) {
        const long Npart = (long)gridDim.x * 128;
        const long M = (long)gridDim.y * 128;
        const int nzb = gridDim.z / kSplit;
        float* dst = Cpart + ((long)zs * nzb + zb) * M * Npart;
#pragma unroll
        for (int mt = 0; mt < 4; mt++)
#pragma unroll
            for (int nt = 0; nt < 4; nt++) {
                float* d = acc[mt][nt];
                const long gm = row0 + wm * 64 + mt * 16 + (lane >> 2);
                const long gn = col0 + wn * 32 + nt * 8 + (lane & 3) * 2;
#pragma unroll
                for (int half = 0; half < 2; half++) {
                    const long r = gm + half * 8;
                    *(float2*)(dst + r * Npart + gn) =
                        make_float2(d[half * 2 + 0] * alpha, d[half * 2 + 1] * alpha);
                }
            }
        return;
    }

    float* Cz = C ? C + sC * zb : nullptr;
    f16* Hz = Chi ? Chi + sC * zb : nullptr;
    const float* bz = bias ? bias + (long)zb * sBias : nullptr;

#pragma unroll
    for (int mt = 0; mt < 4; mt++)
#pragma unroll
        for (int nt = 0; nt < 4; nt++) {
            float* d = acc[mt][nt];
            const long gm = row0 + wm * 64 + mt * 16 + (lane >> 2);
            const long gn = col0 + wn * 32 + nt * 8 + (lane & 3) * 2;
            float b0 = 0.0f, b1 = 0.0f;
            if (bz) { b0 = __ldg(bz + gn); b1 = __ldg(bz + gn + 1); }
#pragma unroll
            for (int half = 0; half < 2; half++) {
                const long r = gm + half * 8;
                float x0 = d[half * 2 + 0] * alpha + b0;
                float x1 = d[half * 2 + 1] * alpha + b1;
                if (relu) { x0 = fmaxf(x0, 0.0f); x1 = fmaxf(x1, 0.0f); }
                const long o = r * ldc + gn;
                if (Cz) *(float2*)(Cz + o) = make_float2(x0, x1);
                if (Hz) {
                    uint32_t wh = (uint32_t)__half_as_ushort(__float2half_rn(x0)) |
                                  ((uint32_t)__half_as_ushort(__float2half_rn(x1)) << 16);
                    *(uint32_t*)(Hz + o) = wh;
                }
            }
        }
}

// =============== split-K combine: out = p0 + p1 (+bias) -> f16 =================
__global__ void __launch_bounds__(256)
combine2(const float* __restrict__ part, long perMat, long total,
         int Npart, f16* __restrict__ outH, int ldc, long sC)
{
    const long i = ((long)blockIdx.x * blockDim.x + threadIdx.x) * 4;
    if (i >= total) return;
    const long zb = i / perMat;
    const long rem = i - zb * perMat;
    const long m = rem / Npart;
    const int n = (int)(rem - m * Npart);
    float4 p0 = *(const float4*)(part + i);
    float4 p1 = *(const float4*)(part + total + i);
    const long o = zb * sC + m * ldc + n;
    uint2 wh;
    wh.x = (uint32_t)__half_as_ushort(__float2half_rn(p0.x + p1.x)) |
           ((uint32_t)__half_as_ushort(__float2half_rn(p0.y + p1.y)) << 16);
    wh.y = (uint32_t)__half_as_ushort(__float2half_rn(p0.z + p1.z)) |
           ((uint32_t)__half_as_ushort(__float2half_rn(p0.w + p1.w)) << 16);
    *(uint2*)(outH + o) = wh;
}

// ====== fused: h = LayerNorm(h + (p0 + p1 + bias)) * g + b, emit f32 + f16 =====
// partials layout from split-K=2 GEMM with batch 1: part[zs][m][DIM].
__global__ void __launch_bounds__(256)
add_ln_combine(float* __restrict__ h, const float* __restrict__ part,
               const float* __restrict__ bias,
               const float* __restrict__ g, const float* __restrict__ b,
               f16* __restrict__ ohi)
{
    const long row = blockIdx.x;
    float* hp = h + row * (long)DIM;
    const float* p0 = part + row * (long)DIM;
    const float* p1 = part + (long)SEQ * DIM + row * (long)DIM;
    const int tid = threadIdx.x;

    float v[4];
    float sum = 0.0f;
#pragma unroll
    for (int i = 0; i < 4; i++) {
        const int c = tid + i * 256;
        v[i] = hp[c] + (p0[c] + p1[c] + bias[c]);
        sum += v[i];
    }
    __shared__ float red[256];
    red[tid] = sum;
    __syncthreads();
    for (int s = 128; s > 0; s >>= 1) {
        if (tid < s) red[tid] += red[tid + s];
        __syncthreads();
    }
    const float mu = red[0] * (1.0f / DIM);
    __syncthreads();

    float vs = 0.0f;
#pragma unroll
    for (int i = 0; i < 4; i++) {
        const float d = v[i] - mu;
        vs += d * d;
    }
    red[tid] = vs;
    __syncthreads();
    for (int s = 128; s > 0; s >>= 1) {
        if (tid < s) red[tid] += red[tid + s];
        __syncthreads();
    }
    const float inv = rsqrtf(red[0] * (1.0f / DIM) + LN_EPS);
    __syncthreads();
#pragma unroll
    for (int i = 0; i < 4; i++) {
        const int c = tid + i * 256;
        float y = g[c] * (v[i] - mu) * inv + b[c];
        hp[c] = y;
        ohi[row * (long)DIM + c] = __float2half_rn(y);
    }
}

// ============= transpose f32 -> f16 (hi only): [R][C] -> [C][R] ================
__global__ void __launch_bounds__(256)
transpose_f32_f16(const float* __restrict__ in, f16* __restrict__ ohi,
                  int R, int Ccols, long sIn, long sOut)
{
    __shared__ float t[32][33];
    const float* ip = in + sIn * blockIdx.z;
    const int c0 = blockIdx.x * 32, r0 = blockIdx.y * 32;
    const int tx = threadIdx.x & 31, ty = threadIdx.x >> 5;
#pragma unroll
    for (int j = 0; j < 32; j += 8)
        t[ty + j][tx] = ip[(long)(r0 + ty + j) * Ccols + c0 + tx];
    __syncthreads();
#pragma unroll
    for (int j = 0; j < 32; j += 8) {
        long o = sOut * blockIdx.z + (long)(c0 + ty + j) * R + r0 + tx;
        ohi[o] = __float2half_rn(t[tx][ty + j]);
    }
}

// ============= transpose f32 -> f16 hi/lo: [R][C] -> [C][R] (for Wh) ===========
__global__ void __launch_bounds__(256)
transpose_split(const float* __restrict__ in, f16* __restrict__ ohi, f16* __restrict__ olo,
                int R, int Ccols, long sIn, long sOut)
{
    __shared__ float t[32][33];
    const float* ip = in + sIn * blockIdx.z;
    const int c0 = blockIdx.x * 32, r0 = blockIdx.y * 32;
    const int tx = threadIdx.x & 31, ty = threadIdx.x >> 5;
#pragma unroll
    for (int j = 0; j < 32; j += 8)
        t[ty + j][tx] = ip[(long)(r0 + ty + j) * Ccols + c0 + tx];
    __syncthreads();
#pragma unroll
    for (int j = 0; j < 32; j += 8) {
        float x = t[tx][ty + j];
        f16 h, l; split2(x, h, l);
        long o = sOut * blockIdx.z + (long)(c0 + ty + j) * R + r0 + tx;
        ohi[o] = h; olo[o] = l;
    }
}

// ========== plain f16 cast of Wq|Wk|Wv into [qkv][l][in][out] =================
__global__ void __launch_bounds__(256)
split_plain_qkv(const float* __restrict__ Wq, const float* __restrict__ Wk,
                const float* __restrict__ Wv, f16* __restrict__ ohi)
{
    const long DDL = (long)NLAYER * DIM * DIM;
    const long idx = (long)blockIdx.x * blockDim.x + threadIdx.x;
    if (idx >= 3 * DDL) return;
    const int w = (int)(idx / DDL);
    const long r = idx - (long)w * DDL;
    const float* src = (w == 0) ? Wq : (w == 1) ? Wk : Wv;
    ohi[idx] = __float2half_rn(src[r]);
}

// ================ f16 transpose: [R][C] -> [C][R] ==============================
__global__ void __launch_bounds__(256)
transpose_hi(const f16* __restrict__ ihi, f16* __restrict__ ohi,
             int R, int Ccols, long sIn, long sOut)
{
    __shared__ unsigned short t[32][33];
    const int c0 = blockIdx.x * 32, r0 = blockIdx.y * 32;
    const int tx = threadIdx.x & 31, ty = threadIdx.x >> 5;
    const f16* a = ihi + sIn * blockIdx.z;
    f16* o = ohi + sOut * blockIdx.z;
#pragma unroll
    for (int j = 0; j < 32; j += 8)
        t[ty + j][tx] = __half_as_ushort(a[(long)(r0 + ty + j) * Ccols + c0 + tx]);
    __syncthreads();
#pragma unroll
    for (int j = 0; j < 32; j += 8)
        o[(long)(c0 + ty + j) * R + r0 + tx] = __ushort_as_half(t[tx][ty + j]);
}

// ============= fused head bias: b'[l][qkv][a][e] = b_qkv . Wh[l][a][:,e] + bh ==
__global__ void __launch_bounds__(256)
bias_head_kernel(const float* __restrict__ bq, const float* __restrict__ bk,
                 const float* __restrict__ bv, const float* __restrict__ bh,
                 const f16* __restrict__ wht_hi, const f16* __restrict__ wht_lo,
                 float* __restrict__ out)
{
    const int warpId = (blockIdx.x * blockDim.x + threadIdx.x) >> 5;
    const int lane = threadIdx.x & 31;
    const int total = NLAYER * 3 * NHEAD * DHEAD;
    if (warpId >= total) return;
    const int e = warpId & (DHEAD - 1);
    const int a = (warpId / DHEAD) & (NHEAD - 1);
    const int qkv = (warpId / (DHEAD * NHEAD)) % 3;
    const int l = warpId / (DHEAD * NHEAD * 3);
    const float* bsrc = ((qkv == 0) ? bq : (qkv == 1) ? bk : bv) + (long)l * DIM;
    const long wrow = (((long)l * NHEAD + a) * DHEAD + e) * DIM;
    float s = 0.0f;
    for (int i = lane; i < DIM; i += 32)
        s += bsrc[i] * (__half2float(wht_hi[wrow + i]) + __half2float(wht_lo[wrow + i]));
#pragma unroll
    for (int off = 16; off > 0; off >>= 1) s += __shfl_down_sync(0xFFFFFFFFu, s, off);
    if (lane == 0) out[warpId] = s + bh[((long)l * NHEAD + a) * DHEAD + e];
}

// ======== fused prologue misc: copy + f16 cast of hidden =======================
__global__ void __launch_bounds__(256)
prep_misc(const float* __restrict__ hidden, float* __restrict__ h,
          f16* __restrict__ dhi)
{
    const int idx = blockIdx.x * blockDim.x + threadIdx.x;
    if (idx < SEQ * DIM) {
        float v = hidden[idx];
        h[idx] = v;
        dhi[idx] = __float2half_rn(v);
    }
}

// ============ softmax over rows (f16 in, in-place f16 out) =====================
__global__ void __launch_bounds__(256)
softmax_kernel(f16* __restrict__ s16)
{
    const size_t base = (size_t)blockIdx.x * SEQ;
    const int tid = threadIdx.x;

    float v[12];
    float mx = -1e30f;
#pragma unroll
    for (int i = 0; i < 12; i++) {
        v[i] = __half2float(s16[base + tid + i * 256]);
        mx = fmaxf(mx, v[i]);
    }
    __shared__ float red[256];
    red[tid] = mx;
    __syncthreads();
    for (int s = 128; s > 0; s >>= 1) {
        if (tid < s) red[tid] = fmaxf(red[tid], red[tid + s]);
        __syncthreads();
    }
    mx = red[0];
    __syncthreads();

    float sum = 0.0f;
#pragma unroll
    for (int i = 0; i < 12; i++) {
        v[i] = __expf(v[i] - mx);
        sum += v[i];
    }
    red[tid] = sum;
    __syncthreads();
    for (int s = 128; s > 0; s >>= 1) {
        if (tid < s) red[tid] += red[tid + s];
        __syncthreads();
    }
    const float inv = 1.0f / red[0];
#pragma unroll
    for (int i = 0; i < 12; i++)
        s16[base + tid + i * 256] = __float2half_rn(v[i] * inv);
}

// ======================= output heads =======================
__global__ void __launch_bounds__(256)
heads_kernel(const float* __restrict__ h, const float* __restrict__ Whead,
             const float* __restrict__ bhead, const int* __restrict__ nev,
             const int* __restrict__ nag, float* __restrict__ out, int total)
{
    const int warpId = (blockIdx.x * blockDim.x + threadIdx.x) >> 5;
    const int lane = threadIdx.x & 31;
    if (warpId >= total) return;
    const int NEv = *nev;
    const int NAg = *nag;
    int headIdx, token;
    if (warpId < 3 * NAg) {
        headIdx = warpId / NAg;
        token = NEv + warpId % NAg;
    } else {
        headIdx = 3;
        token = warpId - 3 * NAg;
    }
    const float* hr = h + (long)token * DIM;
    const float* w = Whead + (long)headIdx * DIM;
    float s = 0.0f;
    for (int i = lane; i < DIM; i += 32) s = fmaf(hr[i], w[i], s);
#pragma unroll
    for (int off = 16; off > 0; off >>= 1) s += __shfl_down_sync(0xFFFFFFFFu, s, off);
    if (lane == 0) out[warpId] = s + bhead[headIdx];
}

// ======================= host orchestration =======================
static void tcg(const f16* A, int lda, long sAo, long sAi,
                const f16* B, int ldb, long sBo, long sBi,
                const float* bias, long sBias, int nB,
                float* C, f16* Chi, int ldc, long sC,
                int M, int N, int K, int batch, float alpha, int relu,
                int kSplit = 1, float* Cpart = nullptr)
{
    dim3 grid(N / 128, M / 128, batch * kSplit);
    mma_gemm<<<grid, 256, GSMEM_BYTES>>>(A, lda, sAo, sAi, B, ldb, sBo, sBi,
                                         bias, sBias, nB, C, Chi, ldc, sC, K, alpha, relu,
                                         kSplit, Cpart);
}

#define SYM(var, name) cudaGetSymbolAddress((void**)&var, name)

extern "C" void kernel_launch(void* const* d_in, const int* in_sizes, int n_in,
                              void* d_out, int out_size)
{
    const float* hidden = (const float*)d_in[0];
    const float* Wq = (const float*)d_in[1];
    const float* bq = (const float*)d_in[2];
    const float* Wk = (const float*)d_in[3];
    const float* bk = (const float*)d_in[4];
    const float* Wv = (const float*)d_in[5];
    const float* bv = (const float*)d_in[6];
    const float* Wh = (const float*)d_in[7];
    const float* bh = (const float*)d_in[8];
    const float* Wo = (const float*)d_in[9];
    const float* bo = (const float*)d_in[10];
    const float* g1 = (const float*)d_in[11];
    const float* b1n = (const float*)d_in[12];
    const float* g2 = (const float*)d_in[13];
    const float* b2n = (const float*)d_in[14];
    const float* Wf1 = (const float*)d_in[15];
    const float* bf1 = (const float*)d_in[16];
    const float* Wf2 = (const float*)d_in[17];
    const float* bf2 = (const float*)d_in[18];
    const float* Whead = (const float*)d_in[19];
    const float* bhead = (const float*)d_in[20];
    const int* n_events = (const int*)d_in[21];
    const int* n_agents = (const int*)d_in[22];
    (void)in_sizes; (void)n_in;

    cudaFuncSetAttribute(mma_gemm, cudaFuncAttributeMaxDynamicSharedMemorySize, GSMEM_BYTES);

    float *h, *bprime, *spl;
    SYM(h, g_h); SYM(bprime, g_bprime); SYM(spl, g_split);
    f16 *h_hi, *qkvh, *vht, *ctx, *f1, *at;
    SYM(h_hi, g_h_hi); SYM(qkvh, g_qkvh); SYM(vht, g_vht);
    SYM(ctx, g_ctx); SYM(f1, g_f1); SYM(at, g_at);
    f16 *wsplit, *wpt, *wot, *wht_hi, *wht_lo, *w1t, *w2t;
    SYM(wsplit, g_wsplit); SYM(wpt, g_wpt); SYM(wot, g_wot);
    SYM(wht_hi, g_wht_hi); SYM(wht_lo, g_wht_lo);
    SYM(w1t, g_w1t); SYM(w2t, g_w2t);

    const long DD = (long)DIM * DIM;
    const long SD = (long)SEQ * DIM;
    const long SS = (long)SEQ * SEQ;
    const long SDh = (long)SEQ * DHEAD;
    const long WHL = (long)NHEAD * DHEAD * DIM;
    const long HD = (long)DHEAD * DIM;

    // ---- prologue ----
    transpose_f32_f16<<<dim3(DIM / 32, DIM / 32, NLAYER), 256>>>(Wo, wot, DIM, DIM, DD, DD);
    transpose_split<<<dim3(DHEAD / 32, DIM / 32, NLAYER * NHEAD), 256>>>(
        Wh, wht_hi, wht_lo, DIM, DHEAD, HD, HD);
    transpose_f32_f16<<<dim3(2 * DIM / 32, DIM / 32, NLAYER), 256>>>(Wf1, w1t, DIM, 2 * DIM, 2 * DD, 2 * DD);
    transpose_f32_f16<<<dim3(DIM / 32, 2 * DIM / 32, NLAYER), 256>>>(Wf2, w2t, 2 * DIM, DIM, 2 * DD, 2 * DD);
    {
        const long totalW = 3 * (long)NLAYER * DD;
        split_plain_qkv<<<(int)((totalW + 255) / 256), 256>>>(Wq, Wk, Wv, wsplit);
    }
    prep_misc<<<(SEQ * DIM + 255) / 256, 256>>>(hidden, h, h_hi);
    {
        const int totalB = NLAYER * 3 * NHEAD * DHEAD;
        bias_head_kernel<<<(totalB * 32 + 255) / 256, 256>>>(bq, bk, bv, bh, wht_hi, wht_lo, bprime);
    }
    // W'^T[qkv][l][a] = wht[l][a] (DHEADxDIM) x Wq/k/v
    for (int qkv = 0; qkv < 3; qkv++) {
        tcg(wht_hi, DIM, WHL, HD,
            wsplit + (long)qkv * NLAYER * DD, DIM, DD, 0,
            nullptr, 0, NHEAD,
            nullptr, wpt + (long)qkv * NLAYER * WHL,
            DIM, HD, DHEAD, DIM, DIM, NLAYER * NHEAD, 1.0f, 0);
    }

    const float attn_scale = 1.0f / 16.0f;

    for (int l = 0; l < NLAYER; l++) {
        // fused QKV+head projections: qkvh[qkv][a] = h @ W'[l][qkv][a] + b'
        tcg(h_hi, DIM, 0, 0,
            wpt + l * WHL, DIM, (long)NLAYER * WHL, HD,
            bprime + (long)l * 3 * NHEAD * DHEAD, DHEAD, NHEAD,
            nullptr, qkvh, DHEAD, SDh, SEQ, DHEAD, DIM, 3 * NHEAD, 1.0f, 0);
        // Vh [head][t][e] -> [head][e][t]
        transpose_hi<<<dim3(DHEAD / 32, SEQ / 32, NHEAD), 256>>>(
            qkvh + 2 * SD, vht, SEQ, DHEAD, SDh, SDh);
        // scores = scale * Qh @ Kh^T -> f16
        tcg(qkvh, DHEAD, SDh, 0,
            qkvh + SD, DHEAD, SDh, 0,
            nullptr, 0, 1,
            nullptr, at, SEQ, SS, SEQ, SEQ, DHEAD, NHEAD, attn_scale, 0);
        // softmax in-place
        softmax_kernel<<<NHEAD * SEQ, 256>>>(at);
        // ctx = attn @ Vh  (split-K=2 -> combine to f16 [t][a*DHEAD+e])
        tcg(at, SEQ, SS, 0,
            vht, SEQ, SDh, 0,
            nullptr, 0, 1,
            nullptr, nullptr, 0, 0, SEQ, DHEAD, SEQ, NHEAD, 1.0f, 0,
            2, spl);
        {
            const long total = (long)NHEAD * SEQ * DHEAD;
            combine2<<<(int)((total / 4 + 255) / 256), 256>>>(
                spl, SDh, total, DHEAD, ctx, DIM, DHEAD);
        }
        // attn_out partials = ctx @ Wo (split-K=2), then fused combine+bias+LN
        tcg(ctx, DIM, 0, 0,
            wot + l * DD, DIM, 0, 0,
            nullptr, 0, 1,
            nullptr, nullptr, 0, 0, SEQ, DIM, DIM, 1, 1.0f, 0,
            2, spl);
        add_ln_combine<<<SEQ, 256>>>(h, spl, bo + (long)l * DIM,
                                     g1 + (long)l * DIM, b1n + (long)l * DIM, h_hi);
        // FFN
        tcg(h_hi, DIM, 0, 0,
            w1t + l * 2 * DD, DIM, 0, 0,
            bf1 + (long)l * 2 * DIM, 0, 1,
            nullptr, f1, 2 * DIM, 0, SEQ, 2 * DIM, DIM, 1, 1.0f, 1);
        tcg(f1, 2 * DIM, 0, 0,
            w2t + l * 2 * DD, 2 * DIM, 0, 0,
            nullptr, 0, 1,
            nullptr, nullptr, 0, 0, SEQ, DIM, 2 * DIM, 1, 1.0f, 0,
            2, spl);
        add_ln_combine<<<SEQ, 256>>>(h, spl, bf2 + (long)l * DIM,
                                     g2 + (long)l * DIM, b2n + (long)l * DIM, h_hi);
    }

    const int blocks = (out_size * 32 + 255) / 256;
    heads_kernel<<<blocks, 256>>>(h, Whead, bhead, n_events, n_agents, (float*)d_out, out_size);
}

// round 14
// speedup vs baseline: 1.3321x; 1.3321x over previous
#include <cuda_runtime.h>
#include <cuda_fp16.h>
#include <cstdint>
#include <math.h>

#define SEQ 3072
#define DIM 1024
#define NHEAD 4
#define DHEAD 256
#define NLAYER 4
#define LN_EPS 1e-5f
typedef __half f16;

// ======================= scratch (static device arrays) =======================
__device__ float g_h[SEQ * DIM];
__device__ float g_split[2 * SEQ * DIM];                             // split-K partials

__device__ f16 g_h_hi[SEQ * DIM];
__device__ f16 g_qkvh[3 * SEQ * DIM];                                // [qkv][head][t][e]
__device__ f16 g_vht[SEQ * DIM];                                     // [head][e][t]
__device__ f16 g_ctx[SEQ * DIM];                                     // [t][head*DHEAD+e]
__device__ f16 g_f1[SEQ * 2 * DIM];
__device__ f16 g_at[(size_t)NHEAD * SEQ * SEQ];                      // scores/attn

// weights (fp16 hi; wht also keeps lo for the f32-exact bias fold)
__device__ f16 g_wsplit[3 * NLAYER * DIM * DIM];                     // [qkv][l][in][out]
__device__ f16 g_wpt[3 * NLAYER * NHEAD * DHEAD * DIM];              // W'^T [qkv][l][a][e][in]
__device__ f16 g_wot[NLAYER * DIM * DIM];
__device__ f16 g_wht_hi[NLAYER * NHEAD * DHEAD * DIM], g_wht_lo[NLAYER * NHEAD * DHEAD * DIM];
__device__ f16 g_w1t[NLAYER * DIM * 2 * DIM];
__device__ f16 g_w2t[NLAYER * 2 * DIM * DIM];
__device__ float g_bprime[NLAYER * 3 * NHEAD * DHEAD];               // [l][qkv][a][e]

// ======================= helpers =======================
__device__ __forceinline__ uint32_t s2u(const void* p) {
    uint32_t a;
    asm("{ .reg .u64 t; cvta.to.shared.u64 t, %1; cvt.u32.u64 %0, t; }" : "=r"(a) : "l"(p));
    return a;
}
__device__ __forceinline__ void split2(float x, f16& h, f16& l) {
    h = __float2half_rn(x);
    l = __float2half_rn(x - __half2float(h));
}
__device__ __forceinline__ void cp16(uint32_t dst, const void* src) {
    asm volatile("cp.async.cg.shared.global [%0], [%1], 16;" :: "r"(dst), "l"(src) : "memory");
}
#define CP_COMMIT() asm volatile("cp.async.commit_group;" ::: "memory")
#define CP_WAIT(n)  asm volatile("cp.async.wait_group %0;" :: "n"(n) : "memory")

__device__ __forceinline__ void ldm_x4(uint32_t* r, uint32_t addr) {
    asm volatile("ldmatrix.sync.aligned.m8n8.x4.shared.b16 {%0,%1,%2,%3}, [%4];"
                 : "=r"(r[0]), "=r"(r[1]), "=r"(r[2]), "=r"(r[3]) : "r"(addr));
}
__device__ __forceinline__ void mma_f16(float* c, const uint32_t* a, const uint32_t* b) {
    asm volatile(
        "mma.sync.aligned.m16n8k16.row.col.f32.f16.f16.f32 "
        "{%0,%1,%2,%3}, {%4,%5,%6,%7}, {%8,%9}, {%0,%1,%2,%3};"
        : "+f"(c[0]), "+f"(c[1]), "+f"(c[2]), "+f"(c[3])
        : "r"(a[0]), "r"(a[1]), "r"(a[2]), "r"(a[3]), "r"(b[0]), "r"(b[1]));
}

// ======================= fp16 mma.sync GEMM =======================
// C[m][n] = alpha * sum_k A[m][k]*B[n][k] + bias[n]   (A, B fp16; f32 accum)
// Tile 128x128, BK=64, 3-stage cp.async (32KB/stage: A 16K | B 16K), SW128, occ 1.
// Optional split-K: grid.z = batch*kSplit; partials Cpart[(zs*nzb+zb)*M*Npart + ...].
#define GSMEM_BYTES 98304
#define STAGE_BYTES 32768u

__global__ void __launch_bounds__(256, 1)
mma_gemm(const f16* __restrict__ A, int lda, long sAo, long sAi,
         const f16* __restrict__ B, int ldb, long sBo, long sBi,
         const float* __restrict__ bias, long sBias, int nB,
         float* __restrict__ C, f16* __restrict__ Chi,
         int ldc, long sC, int K, float alpha, int relu,
         int kSplit, float* __restrict__ Cpart)
{
    extern __shared__ char sm[];
    const uint32_t sb = s2u(sm);
    const int tid = threadIdx.x;
    const int wid = tid >> 5;
    const int lane = tid & 31;
    const int wm = wid >> 2;
    const int wn = wid & 3;
    int zb = blockIdx.z;
    int zs = 0;
    if (kSplit > 1) { zs = zb % kSplit; zb /= kSplit; }
    const int zo = zb / nB;
    const int zi = zb - zo * nB;
    const long row0 = (long)blockIdx.y * 128;
    const long col0 = (long)blockIdx.x * 128;

    const int Ksub = K / kSplit;
    const long koff = (long)zs * Ksub;

    A += zo * sAo + zi * sAi + koff;
    B += zo * sBo + zi * sBi + koff;

    const int nch = Ksub >> 6;

    auto load_chunk = [&](int ch, int stage) {
        const long k0 = (long)ch << 6;
#pragma unroll
        for (int i = 0; i < 8; i++) {
            const int u = tid + (i << 8);
            const int t = u >> 10;          // 0=A 1=B
            const int q = u & 1023;         // row*8 + seg
            const long r = q >> 3;
            const int sg = (q & 7) << 3;
            const f16* p = (t == 0) ? (A + (row0 + r) * lda) : (B + (col0 + r) * ldb);
            uint32_t off = (uint32_t)(q << 4);
            off ^= (off >> 3) & 0x70;
            cp16(sb + (uint32_t)stage * STAGE_BYTES + (uint32_t)t * 16384u + off, p + k0 + sg);
        }
        CP_COMMIT();
    };

    float acc[4][4][4];
#pragma unroll
    for (int a = 0; a < 4; a++)
#pragma unroll
        for (int b = 0; b < 4; b++)
#pragma unroll
            for (int c = 0; c < 4; c++) acc[a][b][c] = 0.0f;

    load_chunk(0, 0);
    load_chunk(1, 1);

    for (int ch = 0; ch < nch; ch++) {
        if (ch + 2 < nch) {
            load_chunk(ch + 2, (ch + 2) % 3);
            CP_WAIT(2);
        } else {
            CP_WAIT(0);
        }
        __syncthreads();

        const uint32_t stg = sb + (uint32_t)(ch % 3) * STAGE_BYTES;

#pragma unroll
        for (int ks = 0; ks < 4; ks++) {
            uint32_t ah[4][4], bh[2][4];
#pragma unroll
            for (int mt = 0; mt < 4; mt++) {
                const int row = wm * 64 + mt * 16 + (lane & 15);
                const int colb = ks * 32 + ((lane >> 4) << 4);
                uint32_t off = (uint32_t)(row * 128 + colb);
                off ^= (off >> 3) & 0x70;
                ldm_x4(ah[mt], stg + off);
            }
#pragma unroll
            for (int np = 0; np < 2; np++) {
                const int row = wn * 32 + np * 16 + (lane & 7) + ((lane >> 4) << 3);
                const int colb = ks * 32 + (((lane >> 3) & 1) << 4);
                uint32_t off = (uint32_t)(row * 128 + colb);
                off ^= (off >> 3) & 0x70;
                ldm_x4(bh[np], stg + 16384u + off);
            }
#pragma unroll
            for (int mt = 0; mt < 4; mt++)
#pragma unroll
                for (int nt = 0; nt < 4; nt++) {
                    const uint32_t* bhp = &bh[nt >> 1][(nt & 1) * 2];
                    mma_f16(acc[mt][nt], ah[mt], bhp);
                }
        }
        __syncthreads();
    }

    // -------- epilogue --------
    if (kSplit > 1) {
        const long Npart = (long)gridDim.x * 128;
        const long M = (long)gridDim.y * 128;
        const int nzb = gridDim.z / kSplit;
        float* dst = Cpart + ((long)zs * nzb + zb) * M * Npart;
#pragma unroll
        for (int mt = 0; mt < 4; mt++)
#pragma unroll
            for (int nt = 0; nt < 4; nt++) {
                float* d = acc[mt][nt];
                const long gm = row0 + wm * 64 + mt * 16 + (lane >> 2);
                const long gn = col0 + wn * 32 + nt * 8 + (lane & 3) * 2;
#pragma unroll
                for (int half = 0; half < 2; half++) {
                    const long r = gm + half * 8;
                    *(float2*)(dst + r * Npart + gn) =
                        make_float2(d[half * 2 + 0] * alpha, d[half * 2 + 1] * alpha);
                }
            }
        return;
    }

    float* Cz = C ? C + sC * zb : nullptr;
    f16* Hz = Chi ? Chi + sC * zb : nullptr;
    const float* bz = bias ? bias + (long)zb * sBias : nullptr;

#pragma unroll
    for (int mt = 0; mt < 4; mt++)
#pragma unroll
        for (int nt = 0; nt < 4; nt++) {
            float* d = acc[mt][nt];
            const long gm = row0 + wm * 64 + mt * 16 + (lane >> 2);
            const long gn = col0 + wn * 32 + nt * 8 + (lane & 3) * 2;
            float b0 = 0.0f, b1 = 0.0f;
            if (bz) { b0 = __ldg(bz + gn); b1 = __ldg(bz + gn + 1); }
#pragma unroll
            for (int half = 0; half < 2; half++) {
                const long r = gm + half * 8;
                float x0 = d[half * 2 + 0] * alpha + b0;
                float x1 = d[half * 2 + 1] * alpha + b1;
                if (relu) { x0 = fmaxf(x0, 0.0f); x1 = fmaxf(x1, 0.0f); }
                const long o = r * ldc + gn;
                if (Cz) *(float2*)(Cz + o) = make_float2(x0, x1);
                if (Hz) {
                    uint32_t wh = (uint32_t)__half_as_ushort(__float2half_rn(x0)) |
                                  ((uint32_t)__half_as_ushort(__float2half_rn(x1)) << 16);
                    *(uint32_t*)(Hz + o) = wh;
                }
            }
        }
}

// =============== split-K combine: out = p0 + p1 -> f16 ========================
__global__ void __launch_bounds__(256)
combine2(const float* __restrict__ part, long perMat, long total,
         int Npart, f16* __restrict__ outH, int ldc, long sC)
{
    const long i = ((long)blockIdx.x * blockDim.x + threadIdx.x) * 4;
    if (i >= total) return;
    const long zb = i / perMat;
    const long rem = i - zb * perMat;
    const long m = rem / Npart;
    const int n = (int)(rem - m * Npart);
    float4 p0 = *(const float4*)(part + i);
    float4 p1 = *(const float4*)(part + total + i);
    const long o = zb * sC + m * ldc + n;
    uint2 wh;
    wh.x = (uint32_t)__half_as_ushort(__float2half_rn(p0.x + p1.x)) |
           ((uint32_t)__half_as_ushort(__float2half_rn(p0.y + p1.y)) << 16);
    wh.y = (uint32_t)__half_as_ushort(__float2half_rn(p0.z + p1.z)) |
           ((uint32_t)__half_as_ushort(__float2half_rn(p0.w + p1.w)) << 16);
    *(uint2*)(outH + o) = wh;
}

// ====== fused: h = LayerNorm(h + (p0 + p1 + bias)) * g + b, emit f32 + f16 =====
// partials layout from split-K=2 GEMM with batch 1: part[zs][m][DIM].
__global__ void __launch_bounds__(256)
add_ln_combine(float* __restrict__ h, const float* __restrict__ part,
               const float* __restrict__ bias,
               const float* __restrict__ g, const float* __restrict__ b,
               f16* __restrict__ ohi)
{
    const long row = blockIdx.x;
    float* hp = h + row * (long)DIM;
    const float* p0 = part + row * (long)DIM;
    const float* p1 = part + (long)SEQ * DIM + row * (long)DIM;
    const int tid = threadIdx.x;

    float v[4];
    float sum = 0.0f;
#pragma unroll
    for (int i = 0; i < 4; i++) {
        const int c = tid + i * 256;
        v[i] = hp[c] + (p0[c] + p1[c] + bias[c]);
        sum += v[i];
    }
    __shared__ float red[256];
    red[tid] = sum;
    __syncthreads();
    for (int s = 128; s > 0; s >>= 1) {
        if (tid < s) red[tid] += red[tid + s];
        __syncthreads();
    }
    const float mu = red[0] * (1.0f / DIM);
    __syncthreads();

    float vs = 0.0f;
#pragma unroll
    for (int i = 0; i < 4; i++) {
        const float d = v[i] - mu;
        vs += d * d;
    }
    red[tid] = vs;
    __syncthreads();
    for (int s = 128; s > 0; s >>= 1) {
        if (tid < s) red[tid] += red[tid + s];
        __syncthreads();
    }
    const float inv = rsqrtf(red[0] * (1.0f / DIM) + LN_EPS);
    __syncthreads();
#pragma unroll
    for (int i = 0; i < 4; i++) {
        const int c = tid + i * 256;
        float y = g[c] * (v[i] - mu) * inv + b[c];
        hp[c] = y;
        ohi[row * (long)DIM + c] = __float2half_rn(y);
    }
}

// ============= transpose f32 -> f16 (hi only): [R][C] -> [C][R] ================
__global__ void __launch_bounds__(256)
transpose_f32_f16(const float* __restrict__ in, f16* __restrict__ ohi,
                  int R, int Ccols, long sIn, long sOut)
{
    __shared__ float t[32][33];
    const float* ip = in + sIn * blockIdx.z;
    const int c0 = blockIdx.x * 32, r0 = blockIdx.y * 32;
    const int tx = threadIdx.x & 31, ty = threadIdx.x >> 5;
#pragma unroll
    for (int j = 0; j < 32; j += 8)
        t[ty + j][tx] = ip[(long)(r0 + ty + j) * Ccols + c0 + tx];
    __syncthreads();
#pragma unroll
    for (int j = 0; j < 32; j += 8) {
        long o = sOut * blockIdx.z + (long)(c0 + ty + j) * R + r0 + tx;
        ohi[o] = __float2half_rn(t[tx][ty + j]);
    }
}

// ============= transpose f32 -> f16 hi/lo: [R][C] -> [C][R] (for Wh) ===========
__global__ void __launch_bounds__(256)
transpose_split(const float* __restrict__ in, f16* __restrict__ ohi, f16* __restrict__ olo,
                int R, int Ccols, long sIn, long sOut)
{
    __shared__ float t[32][33];
    const float* ip = in + sIn * blockIdx.z;
    const int c0 = blockIdx.x * 32, r0 = blockIdx.y * 32;
    const int tx = threadIdx.x & 31, ty = threadIdx.x >> 5;
#pragma unroll
    for (int j = 0; j < 32; j += 8)
        t[ty + j][tx] = ip[(long)(r0 + ty + j) * Ccols + c0 + tx];
    __syncthreads();
#pragma unroll
    for (int j = 0; j < 32; j += 8) {
        float x = t[tx][ty + j];
        f16 h, l; split2(x, h, l);
        long o = sOut * blockIdx.z + (long)(c0 + ty + j) * R + r0 + tx;
        ohi[o] = h; olo[o] = l;
    }
}

// ========== plain f16 cast of Wq|Wk|Wv into [qkv][l][in][out] =================
__global__ void __launch_bounds__(256)
split_plain_qkv(const float* __restrict__ Wq, const float* __restrict__ Wk,
                const float* __restrict__ Wv, f16* __restrict__ ohi)
{
    const long DDL = (long)NLAYER * DIM * DIM;
    const long idx = (long)blockIdx.x * blockDim.x + threadIdx.x;
    if (idx >= 3 * DDL) return;
    const int w = (int)(idx / DDL);
    const long r = idx - (long)w * DDL;
    const float* src = (w == 0) ? Wq : (w == 1) ? Wk : Wv;
    ohi[idx] = __float2half_rn(src[r]);
}

// ================ f16 transpose: [R][C] -> [C][R] ==============================
__global__ void __launch_bounds__(256)
transpose_hi(const f16* __restrict__ ihi, f16* __restrict__ ohi,
             int R, int Ccols, long sIn, long sOut)
{
    __shared__ unsigned short t[32][33];
    const int c0 = blockIdx.x * 32, r0 = blockIdx.y * 32;
    const int tx = threadIdx.x & 31, ty = threadIdx.x >> 5;
    const f16* a = ihi + sIn * blockIdx.z;
    f16* o = ohi + sOut * blockIdx.z;
#pragma unroll
    for (int j = 0; j < 32; j += 8)
        t[ty + j][tx] = __half_as_ushort(a[(long)(r0 + ty + j) * Ccols + c0 + tx]);
    __syncthreads();
#pragma unroll
    for (int j = 0; j < 32; j += 8)
        o[(long)(c0 + ty + j) * R + r0 + tx] = __ushort_as_half(t[tx][ty + j]);
}

// ============= fused head bias: b'[l][qkv][a][e] = b_qkv . Wh[l][a][:,e] + bh ==
__global__ void __launch_bounds__(256)
bias_head_kernel(const float* __restrict__ bq, const float* __restrict__ bk,
                 const float* __restrict__ bv, const float* __restrict__ bh,
                 const f16* __restrict__ wht_hi, const f16* __restrict__ wht_lo,
                 float* __restrict__ out)
{
    const int warpId = (blockIdx.x * blockDim.x + threadIdx.x) >> 5;
    const int lane = threadIdx.x & 31;
    const int total = NLAYER * 3 * NHEAD * DHEAD;
    if (warpId >= total) return;
    const int e = warpId & (DHEAD - 1);
    const int a = (warpId / DHEAD) & (NHEAD - 1);
    const int qkv = (warpId / (DHEAD * NHEAD)) % 3;
    const int l = warpId / (DHEAD * NHEAD * 3);
    const float* bsrc = ((qkv == 0) ? bq : (qkv == 1) ? bk : bv) + (long)l * DIM;
    const long wrow = (((long)l * NHEAD + a) * DHEAD + e) * DIM;
    float s = 0.0f;
    for (int i = lane; i < DIM; i += 32)
        s += bsrc[i] * (__half2float(wht_hi[wrow + i]) + __half2float(wht_lo[wrow + i]));
#pragma unroll
    for (int off = 16; off > 0; off >>= 1) s += __shfl_down_sync(0xFFFFFFFFu, s, off);
    if (lane == 0) out[warpId] = s + bh[((long)l * NHEAD + a) * DHEAD + e];
}

// ======== fused prologue misc: copy + f16 cast of hidden =======================
__global__ void __launch_bounds__(256)
prep_misc(const float* __restrict__ hidden, float* __restrict__ h,
          f16* __restrict__ dhi)
{
    const int idx = blockIdx.x * blockDim.x + threadIdx.x;
    if (idx < SEQ * DIM) {
        float v = hidden[idx];
        h[idx] = v;
        dhi[idx] = __float2half_rn(v);
    }
}

// ============ softmax over rows (f16 in, in-place f16 out) =====================
__global__ void __launch_bounds__(256)
softmax_kernel(f16* __restrict__ s16)
{
    const size_t base = (size_t)blockIdx.x * SEQ;
    const int tid = threadIdx.x;

    float v[12];
    float mx = -1e30f;
#pragma unroll
    for (int i = 0; i < 12; i++) {
        v[i] = __half2float(s16[base + tid + i * 256]);
        mx = fmaxf(mx, v[i]);
    }
    __shared__ float red[256];
    red[tid] = mx;
    __syncthreads();
    for (int s = 128; s > 0; s >>= 1) {
        if (tid < s) red[tid] = fmaxf(red[tid], red[tid + s]);
        __syncthreads();
    }
    mx = red[0];
    __syncthreads();

    float sum = 0.0f;
#pragma unroll
    for (int i = 0; i < 12; i++) {
        v[i] = __expf(v[i] - mx);
        sum += v[i];
    }
    red[tid] = sum;
    __syncthreads();
    for (int s = 128; s > 0; s >>= 1) {
        if (tid < s) red[tid] += red[tid + s];
        __syncthreads();
    }
    const float inv = 1.0f / red[0];
#pragma unroll
    for (int i = 0; i < 12; i++)
        s16[base + tid + i * 256] = __float2half_rn(v[i] * inv);
}

// ======================= output heads =======================
__global__ void __launch_bounds__(256)
heads_kernel(const float* __restrict__ h, const float* __restrict__ Whead,
             const float* __restrict__ bhead, const int* __restrict__ nev,
             const int* __restrict__ nag, float* __restrict__ out, int total)
{
    const int warpId = (blockIdx.x * blockDim.x + threadIdx.x) >> 5;
    const int lane = threadIdx.x & 31;
    if (warpId >= total) return;
    const int NEv = *nev;
    const int NAg = *nag;
    int headIdx, token;
    if (warpId < 3 * NAg) {
        headIdx = warpId / NAg;
        token = NEv + warpId % NAg;
    } else {
        headIdx = 3;
        token = warpId - 3 * NAg;
    }
    const float* hr = h + (long)token * DIM;
    const float* w = Whead + (long)headIdx * DIM;
    float s = 0.0f;
    for (int i = lane; i < DIM; i += 32) s = fmaf(hr[i], w[i], s);
#pragma unroll
    for (int off = 16; off > 0; off >>= 1) s += __shfl_down_sync(0xFFFFFFFFu, s, off);
    if (lane == 0) out[warpId] = s + bhead[headIdx];
}

// ======================= host orchestration =======================
static void tcg(const f16* A, int lda, long sAo, long sAi,
                const f16* B, int ldb, long sBo, long sBi,
                const float* bias, long sBias, int nB,
                float* C, f16* Chi, int ldc, long sC,
                int M, int N, int K, int batch, float alpha, int relu,
                int kSplit = 1, float* Cpart = nullptr)
{
    dim3 grid(N / 128, M / 128, batch * kSplit);
    mma_gemm<<<grid, 256, GSMEM_BYTES>>>(A, lda, sAo, sAi, B, ldb, sBo, sBi,
                                         bias, sBias, nB, C, Chi, ldc, sC, K, alpha, relu,
                                         kSplit, Cpart);
}

#define SYM(var, name) cudaGetSymbolAddress((void**)&var, name)

extern "C" void kernel_launch(void* const* d_in, const int* in_sizes, int n_in,
                              void* d_out, int out_size)
{
    const float* hidden = (const float*)d_in[0];
    const float* Wq = (const float*)d_in[1];
    const float* bq = (const float*)d_in[2];
    const float* Wk = (const float*)d_in[3];
    const float* bk = (const float*)d_in[4];
    const float* Wv = (const float*)d_in[5];
    const float* bv = (const float*)d_in[6];
    const float* Wh = (const float*)d_in[7];
    const float* bh = (const float*)d_in[8];
    const float* Wo = (const float*)d_in[9];
    const float* bo = (const float*)d_in[10];
    const float* g1 = (const float*)d_in[11];
    const float* b1n = (const float*)d_in[12];
    const float* g2 = (const float*)d_in[13];
    const float* b2n = (const float*)d_in[14];
    const float* Wf1 = (const float*)d_in[15];
    const float* bf1 = (const float*)d_in[16];
    const float* Wf2 = (const float*)d_in[17];
    const float* bf2 = (const float*)d_in[18];
    const float* Whead = (const float*)d_in[19];
    const float* bhead = (const float*)d_in[20];
    const int* n_events = (const int*)d_in[21];
    const int* n_agents = (const int*)d_in[22];
    (void)in_sizes; (void)n_in;

    cudaFuncSetAttribute(mma_gemm, cudaFuncAttributeMaxDynamicSharedMemorySize, GSMEM_BYTES);

    float *h, *bprime, *spl;
    SYM(h, g_h); SYM(bprime, g_bprime); SYM(spl, g_split);
    f16 *h_hi, *qkvh, *vht, *ctx, *f1, *at;
    SYM(h_hi, g_h_hi); SYM(qkvh, g_qkvh); SYM(vht, g_vht);
    SYM(ctx, g_ctx); SYM(f1, g_f1); SYM(at, g_at);
    f16 *wsplit, *wpt, *wot, *wht_hi, *wht_lo, *w1t, *w2t;
    SYM(wsplit, g_wsplit); SYM(wpt, g_wpt); SYM(wot, g_wot);
    SYM(wht_hi, g_wht_hi); SYM(wht_lo, g_wht_lo);
    SYM(w1t, g_w1t); SYM(w2t, g_w2t);

    const long DD = (long)DIM * DIM;
    const long SD = (long)SEQ * DIM;
    const long SS = (long)SEQ * SEQ;
    const long SDh = (long)SEQ * DHEAD;
    const long WHL = (long)NHEAD * DHEAD * DIM;
    const long HD = (long)DHEAD * DIM;

    // ---- prologue ----
    transpose_f32_f16<<<dim3(DIM / 32, DIM / 32, NLAYER), 256>>>(Wo, wot, DIM, DIM, DD, DD);
    transpose_split<<<dim3(DHEAD / 32, DIM / 32, NLAYER * NHEAD), 256>>>(
        Wh, wht_hi, wht_lo, DIM, DHEAD, HD, HD);
    transpose_f32_f16<<<dim3(2 * DIM / 32, DIM / 32, NLAYER), 256>>>(Wf1, w1t, DIM, 2 * DIM, 2 * DD, 2 * DD);
    transpose_f32_f16<<<dim3(DIM / 32, 2 * DIM / 32, NLAYER), 256>>>(Wf2, w2t, 2 * DIM, DIM, 2 * DD, 2 * DD);
    {
        const long totalW = 3 * (long)NLAYER * DD;
        split_plain_qkv<<<(int)((totalW + 255) / 256), 256>>>(Wq, Wk, Wv, wsplit);
    }
    prep_misc<<<(SEQ * DIM + 255) / 256, 256>>>(hidden, h, h_hi);
    {
        const int totalB = NLAYER * 3 * NHEAD * DHEAD;
        bias_head_kernel<<<(totalB * 32 + 255) / 256, 256>>>(bq, bk, bv, bh, wht_hi, wht_lo, bprime);
    }
    // W'^T[qkv][l][a] = wht[l][a] (DHEADxDIM) x Wq/k/v
    for (int qkv = 0; qkv < 3; qkv++) {
        tcg(wht_hi, DIM, WHL, HD,
            wsplit + (long)qkv * NLAYER * DD, DIM, DD, 0,
            nullptr, 0, NHEAD,
            nullptr, wpt + (long)qkv * NLAYER * WHL,
            DIM, HD, DHEAD, DIM, DIM, NLAYER * NHEAD, 1.0f, 0);
    }

    const float attn_scale = 1.0f / 16.0f;

    for (int l = 0; l < NLAYER; l++) {
        // fused QKV+head projections: qkvh[qkv][a] = h @ W'[l][qkv][a] + b'
        tcg(h_hi, DIM, 0, 0,
            wpt + l * WHL, DIM, (long)NLAYER * WHL, HD,
            bprime + (long)l * 3 * NHEAD * DHEAD, DHEAD, NHEAD,
            nullptr, qkvh, DHEAD, SDh, SEQ, DHEAD, DIM, 3 * NHEAD, 1.0f, 0);
        // Vh [head][t][e] -> [head][e][t]
        transpose_hi<<<dim3(DHEAD / 32, SEQ / 32, NHEAD), 256>>>(
            qkvh + 2 * SD, vht, SEQ, DHEAD, SDh, SDh);
        // scores = scale * Qh @ Kh^T -> f16
        tcg(qkvh, DHEAD, SDh, 0,
            qkvh + SD, DHEAD, SDh, 0,
            nullptr, 0, 1,
            nullptr, at, SEQ, SS, SEQ, SEQ, DHEAD, NHEAD, attn_scale, 0);
        // softmax in-place
        softmax_kernel<<<NHEAD * SEQ, 256>>>(at);
        // ctx = attn @ Vh  (split-K=2 -> combine to f16 [t][a*DHEAD+e])
        tcg(at, SEQ, SS, 0,
            vht, SEQ, SDh, 0,
            nullptr, 0, 1,
            nullptr, nullptr, 0, 0, SEQ, DHEAD, SEQ, NHEAD, 1.0f, 0,
            2, spl);
        {
            const long total = (long)NHEAD * SEQ * DHEAD;
            combine2<<<(int)((total / 4 + 255) / 256), 256>>>(
                spl, SDh, total, DHEAD, ctx, DIM, DHEAD);
        }
        // attn_out partials = ctx @ Wo (split-K=2), then fused combine+bias+LN
        tcg(ctx, DIM, 0, 0,
            wot + l * DD, DIM, 0, 0,
            nullptr, 0, 1,
            nullptr, nullptr, 0, 0, SEQ, DIM, DIM, 1, 1.0f, 0,
            2, spl);
        add_ln_combine<<<SEQ, 256>>>(h, spl, bo + (long)l * DIM,
                                     g1 + (long)l * DIM, b1n + (long)l * DIM, h_hi);
        // FFN
        tcg(h_hi, DIM, 0, 0,
            w1t + l * 2 * DD, DIM, 0, 0,
            bf1 + (long)l * 2 * DIM, 0, 1,
            nullptr, f1, 2 * DIM, 0, SEQ, 2 * DIM, DIM, 1, 1.0f, 1);
        tcg(f1, 2 * DIM, 0, 0,
            w2t + l * 2 * DD, 2 * DIM, 0, 0,
            nullptr, 0, 1,
            nullptr, nullptr, 0, 0, SEQ, DIM, 2 * DIM, 1, 1.0f, 0,
            2, spl);
        add_ln_combine<<<SEQ, 256>>>(h, spl, bf2 + (long)l * DIM,
                                     g2 + (long)l * DIM, b2n + (long)l * DIM, h_hi);
    }

    const int blocks = (out_size * 32 + 255) / 256;
    heads_kernel<<<blocks, 256>>>(h, Whead, bhead, n_events, n_agents, (float*)d_out, out_size);
}

// round 15
// speedup vs baseline: 1.3554x; 1.0175x over previous
#include <cuda_runtime.h>
#include <cuda_fp16.h>
#include <cstdint>
#include <math.h>

#define SEQ 3072
#define DIM 1024
#define NHEAD 4
#define DHEAD 256
#define NLAYER 4
#define LN_EPS 1e-5f
typedef __half f16;

// ======================= scratch (static device arrays) =======================
__device__ float g_h[SEQ * DIM];
__device__ float g_split[4 * SEQ * DIM];                             // split-K partials

__device__ f16 g_h_hi[SEQ * DIM];
__device__ f16 g_qkvh[3 * SEQ * DIM];                                // [qkv][head][t][e]
__device__ f16 g_vht[SEQ * DIM];                                     // [head][e][t]
__device__ f16 g_ctx[SEQ * DIM];                                     // [t][head*DHEAD+e]
__device__ f16 g_f1[SEQ * 2 * DIM];
__device__ f16 g_at[(size_t)NHEAD * SEQ * SEQ];                      // scores/attn

// weights
__device__ f16 g_wsplit[3 * NLAYER * DIM * DIM];                     // [qkv][l][in][out]
__device__ f16 g_wpt[3 * NLAYER * NHEAD * DHEAD * DIM];              // W'^T [qkv][l][a][e][in]
__device__ f16 g_wot[NLAYER * DIM * DIM];
__device__ f16 g_wht_hi[NLAYER * NHEAD * DHEAD * DIM], g_wht_lo[NLAYER * NHEAD * DHEAD * DIM];
__device__ f16 g_w1t[NLAYER * DIM * 2 * DIM];
__device__ f16 g_w2t[NLAYER * 2 * DIM * DIM];
__device__ float g_bprime[NLAYER * 3 * NHEAD * DHEAD];               // [l][qkv][a][e]

// ======================= helpers =======================
__device__ __forceinline__ uint32_t s2u(const void* p) {
    uint32_t a;
    asm("{ .reg .u64 t; cvta.to.shared.u64 t, %1; cvt.u32.u64 %0, t; }" : "=r"(a) : "l"(p));
    return a;
}
__device__ __forceinline__ void split2(float x, f16& h, f16& l) {
    h = __float2half_rn(x);
    l = __float2half_rn(x - __half2float(h));
}
__device__ __forceinline__ void cp16(uint32_t dst, const void* src) {
    asm volatile("cp.async.cg.shared.global [%0], [%1], 16;" :: "r"(dst), "l"(src) : "memory");
}
#define CP_COMMIT() asm volatile("cp.async.commit_group;" ::: "memory")
#define CP_WAIT(n)  asm volatile("cp.async.wait_group %0;" :: "n"(n) : "memory")

__device__ __forceinline__ void ldm_x4(uint32_t* r, uint32_t addr) {
    asm volatile("ldmatrix.sync.aligned.m8n8.x4.shared.b16 {%0,%1,%2,%3}, [%4];"
                 : "=r"(r[0]), "=r"(r[1]), "=r"(r[2]), "=r"(r[3]) : "r"(addr));
}
__device__ __forceinline__ void mma_f16(float* c, const uint32_t* a, const uint32_t* b) {
    asm volatile(
        "mma.sync.aligned.m16n8k16.row.col.f32.f16.f16.f32 "
        "{%0,%1,%2,%3}, {%4,%5,%6,%7}, {%8,%9}, {%0,%1,%2,%3};"
        : "+f"(c[0]), "+f"(c[1]), "+f"(c[2]), "+f"(c[3])
        : "r"(a[0]), "r"(a[1]), "r"(a[2]), "r"(a[3]), "r"(b[0]), "r"(b[1]));
}

// ======================= fp16 mma.sync GEMM (templated M-tile) =================
// C[m][n] = alpha * sum_k A[m][k]*B[n][k] + bias[n]   (A, B fp16; f32 accum)
// CTA tile MT x 128, BK=64, 3-stage cp.async, SW128, occ 1.
// MT=128: 2x4 warps of 64x32.  MT=256: 4x2 warps of 64x64.
// Optional split-K: grid.z = batch*kSplit; partials Cpart[(zs*nzb+zb)*M*Npart+...].
template <int MT>
__global__ void __launch_bounds__(256, 1)
mma_gemm(const f16* __restrict__ A, int lda, long sAo, long sAi,
         const f16* __restrict__ B, int ldb, long sBo, long sBi,
         const float* __restrict__ bias, long sBias, int nB,
         float* __restrict__ C, f16* __restrict__ Chi,
         int ldc, long sC, int K, float alpha, int relu,
         int kSplit, float* __restrict__ Cpart)
{
    constexpr int MW = MT / 64;            // M-warps (2 or 4)
    constexpr int NW = 8 / MW;             // N-warps (4 or 2)
    constexpr int WN = 128 / NW;           // warp N-width (32 or 64)
    constexpr int NT = WN / 8;             // n8-tiles per warp (4 or 8)
    constexpr uint32_t ABYTES = MT * 128;  // A tile bytes/stage
    constexpr uint32_t STG = ABYTES + 16384;
    constexpr int AUNITS = MT * 8;         // 16B units in A tile
    constexpr int UNITS = AUNITS + 1024;   // total 16B units/stage

    extern __shared__ char sm[];
    const uint32_t sb = s2u(sm);
    const int tid = threadIdx.x;
    const int wid = tid >> 5;
    const int lane = tid & 31;
    const int wm = wid / NW;
    const int wn = wid % NW;
    int zb = blockIdx.z;
    int zs = 0;
    if (kSplit > 1) { zs = zb % kSplit; zb /= kSplit; }
    const int zo = zb / nB;
    const int zi = zb - zo * nB;
    const long row0 = (long)blockIdx.y * MT;
    const long col0 = (long)blockIdx.x * 128;

    const int Ksub = K / kSplit;
    const long koff = (long)zs * Ksub;

    A += zo * sAo + zi * sAi + koff;
    B += zo * sBo + zi * sBi + koff;

    const int nch = Ksub >> 6;

    auto load_chunk = [&](int ch, int stage) {
        const long k0 = (long)ch << 6;
#pragma unroll
        for (int i = 0; i < UNITS / 256; i++) {
            const int u = tid + (i << 8);
            const f16* p;
            uint32_t base;
            int q;
            if (u < AUNITS) {
                q = u;
                p = A + (row0 + (q >> 3)) * lda;
                base = 0;
            } else {
                q = u - AUNITS;
                p = B + (col0 + (q >> 3)) * ldb;
                base = ABYTES;
            }
            const int sg = (q & 7) << 3;
            uint32_t off = (uint32_t)(q << 4);
            off ^= (off >> 3) & 0x70;
            cp16(sb + (uint32_t)stage * STG + base + off, p + k0 + sg);
        }
        CP_COMMIT();
    };

    float acc[4][NT][4];
#pragma unroll
    for (int a = 0; a < 4; a++)
#pragma unroll
        for (int b = 0; b < NT; b++)
#pragma unroll
            for (int c = 0; c < 4; c++) acc[a][b][c] = 0.0f;

    load_chunk(0, 0);
    load_chunk(1, 1);

    for (int ch = 0; ch < nch; ch++) {
        if (ch + 2 < nch) {
            load_chunk(ch + 2, (ch + 2) % 3);
            CP_WAIT(2);
        } else {
            CP_WAIT(0);
        }
        __syncthreads();

        const uint32_t stg = sb + (uint32_t)(ch % 3) * STG;

#pragma unroll
        for (int ks = 0; ks < 4; ks++) {
            uint32_t ah[4][4], bh[NT / 2][4];
#pragma unroll
            for (int mt = 0; mt < 4; mt++) {
                const int row = wm * 64 + mt * 16 + (lane & 15);
                const int colb = ks * 32 + ((lane >> 4) << 4);
                uint32_t off = (uint32_t)(row * 128 + colb);
                off ^= (off >> 3) & 0x70;
                ldm_x4(ah[mt], stg + off);
            }
#pragma unroll
            for (int nb = 0; nb < NT / 2; nb++) {
                const int row = wn * WN + nb * 16 + (lane & 7) + ((lane >> 4) << 3);
                const int colb = ks * 32 + (((lane >> 3) & 1) << 4);
                uint32_t off = (uint32_t)(row * 128 + colb);
                off ^= (off >> 3) & 0x70;
                ldm_x4(bh[nb], stg + ABYTES + off);
            }
#pragma unroll
            for (int mt = 0; mt < 4; mt++)
#pragma unroll
                for (int nt = 0; nt < NT; nt++) {
                    const uint32_t* bhp = &bh[nt >> 1][(nt & 1) * 2];
                    mma_f16(acc[mt][nt], ah[mt], bhp);
                }
        }
        __syncthreads();
    }

    // -------- epilogue --------
    if (kSplit > 1) {
        const long Npart = (long)gridDim.x * 128;
        const long Mtot = (long)gridDim.y * MT;
        const int nzb = gridDim.z / kSplit;
        float* dst = Cpart + ((long)zs * nzb + zb) * Mtot * Npart;
#pragma unroll
        for (int mt = 0; mt < 4; mt++)
#pragma unroll
            for (int nt = 0; nt < NT; nt++) {
                float* d = acc[mt][nt];
                const long gm = row0 + wm * 64 + mt * 16 + (lane >> 2);
                const long gn = col0 + wn * WN + nt * 8 + (lane & 3) * 2;
#pragma unroll
                for (int half = 0; half < 2; half++) {
                    const long r = gm + half * 8;
                    *(float2*)(dst + r * Npart + gn) =
                        make_float2(d[half * 2 + 0] * alpha, d[half * 2 + 1] * alpha);
                }
            }
        return;
    }

    float* Cz = C ? C + sC * zb : nullptr;
    f16* Hz = Chi ? Chi + sC * zb : nullptr;
    const float* bz = bias ? bias + (long)zb * sBias : nullptr;

#pragma unroll
    for (int mt = 0; mt < 4; mt++)
#pragma unroll
        for (int nt = 0; nt < NT; nt++) {
            float* d = acc[mt][nt];
            const long gm = row0 + wm * 64 + mt * 16 + (lane >> 2);
            const long gn = col0 + wn * WN + nt * 8 + (lane & 3) * 2;
            float b0 = 0.0f, b1 = 0.0f;
            if (bz) { b0 = __ldg(bz + gn); b1 = __ldg(bz + gn + 1); }
#pragma unroll
            for (int half = 0; half < 2; half++) {
                const long r = gm + half * 8;
                float x0 = d[half * 2 + 0] * alpha + b0;
                float x1 = d[half * 2 + 1] * alpha + b1;
                if (relu) { x0 = fmaxf(x0, 0.0f); x1 = fmaxf(x1, 0.0f); }
                const long o = r * ldc + gn;
                if (Cz) *(float2*)(Cz + o) = make_float2(x0, x1);
                if (Hz) {
                    uint32_t wh = (uint32_t)__half_as_ushort(__float2half_rn(x0)) |
                                  ((uint32_t)__half_as_ushort(__float2half_rn(x1)) << 16);
                    *(uint32_t*)(Hz + o) = wh;
                }
            }
        }
}

// =============== split-K combine: out = sum_s p_s (+bias, relu) -> f16 =========
__global__ void __launch_bounds__(256)
combine_k(const float* __restrict__ part, long perMat, long total, int Npart,
          int kSplit, const float* __restrict__ bias, int relu,
          f16* __restrict__ outH, int ldc, long sC)
{
    const long i = ((long)blockIdx.x * blockDim.x + threadIdx.x) * 4;
    if (i >= total) return;
    const long zb = i / perMat;
    const long rem = i - zb * perMat;
    const long m = rem / Npart;
    const int n = (int)(rem - m * Npart);
    float x0 = 0.0f, x1 = 0.0f, x2 = 0.0f, x3 = 0.0f;
    for (int s = 0; s < kSplit; s++) {
        float4 p = *(const float4*)(part + (long)s * total + i);
        x0 += p.x; x1 += p.y; x2 += p.z; x3 += p.w;
    }
    if (bias) {
        x0 += __ldg(bias + n); x1 += __ldg(bias + n + 1);
        x2 += __ldg(bias + n + 2); x3 += __ldg(bias + n + 3);
    }
    if (relu) {
        x0 = fmaxf(x0, 0.0f); x1 = fmaxf(x1, 0.0f);
        x2 = fmaxf(x2, 0.0f); x3 = fmaxf(x3, 0.0f);
    }
    const long o = zb * sC + m * ldc + n;
    uint2 wh;
    wh.x = (uint32_t)__half_as_ushort(__float2half_rn(x0)) |
           ((uint32_t)__half_as_ushort(__float2half_rn(x1)) << 16);
    wh.y = (uint32_t)__half_as_ushort(__float2half_rn(x2)) |
           ((uint32_t)__half_as_ushort(__float2half_rn(x3)) << 16);
    *(uint2*)(outH + o) = wh;
}

// ====== fused: h = LayerNorm(h + (sum_s p_s + bias)) * g + b, f32 + f16 ========
__global__ void __launch_bounds__(256)
add_ln_combine(float* __restrict__ h, const float* __restrict__ part, int kSplit,
               const float* __restrict__ bias,
               const float* __restrict__ g, const float* __restrict__ b,
               f16* __restrict__ ohi)
{
    const long row = blockIdx.x;
    float* hp = h + row * (long)DIM;
    const int tid = threadIdx.x;

    float v[4];
    float sum = 0.0f;
#pragma unroll
    for (int i = 0; i < 4; i++) {
        const int c = tid + i * 256;
        float acc = bias[c];
        for (int s = 0; s < kSplit; s++)
            acc += part[(long)s * SEQ * DIM + row * (long)DIM + c];
        v[i] = hp[c] + acc;
        sum += v[i];
    }
    __shared__ float red[256];
    red[tid] = sum;
    __syncthreads();
    for (int s = 128; s > 0; s >>= 1) {
        if (tid < s) red[tid] += red[tid + s];
        __syncthreads();
    }
    const float mu = red[0] * (1.0f / DIM);
    __syncthreads();

    float vs = 0.0f;
#pragma unroll
    for (int i = 0; i < 4; i++) {
        const float d = v[i] - mu;
        vs += d * d;
    }
    red[tid] = vs;
    __syncthreads();
    for (int s = 128; s > 0; s >>= 1) {
        if (tid < s) red[tid] += red[tid + s];
        __syncthreads();
    }
    const float inv = rsqrtf(red[0] * (1.0f / DIM) + LN_EPS);
    __syncthreads();
#pragma unroll
    for (int i = 0; i < 4; i++) {
        const int c = tid + i * 256;
        float y = g[c] * (v[i] - mu) * inv + b[c];
        hp[c] = y;
        ohi[row * (long)DIM + c] = __float2half_rn(y);
    }
}

// ============= transpose f32 -> f16 (hi only): [R][C] -> [C][R] ================
__global__ void __launch_bounds__(256)
transpose_f32_f16(const float* __restrict__ in, f16* __restrict__ ohi,
                  int R, int Ccols, long sIn, long sOut)
{
    __shared__ float t[32][33];
    const float* ip = in + sIn * blockIdx.z;
    const int c0 = blockIdx.x * 32, r0 = blockIdx.y * 32;
    const int tx = threadIdx.x & 31, ty = threadIdx.x >> 5;
#pragma unroll
    for (int j = 0; j < 32; j += 8)
        t[ty + j][tx] = ip[(long)(r0 + ty + j) * Ccols + c0 + tx];
    __syncthreads();
#pragma unroll
    for (int j = 0; j < 32; j += 8) {
        long o = sOut * blockIdx.z + (long)(c0 + ty + j) * R + r0 + tx;
        ohi[o] = __float2half_rn(t[tx][ty + j]);
    }
}

// ============= transpose f32 -> f16 hi/lo: [R][C] -> [C][R] (for Wh) ===========
__global__ void __launch_bounds__(256)
transpose_split(const float* __restrict__ in, f16* __restrict__ ohi, f16* __restrict__ olo,
                int R, int Ccols, long sIn, long sOut)
{
    __shared__ float t[32][33];
    const float* ip = in + sIn * blockIdx.z;
    const int c0 = blockIdx.x * 32, r0 = blockIdx.y * 32;
    const int tx = threadIdx.x & 31, ty = threadIdx.x >> 5;
#pragma unroll
    for (int j = 0; j < 32; j += 8)
        t[ty + j][tx] = ip[(long)(r0 + ty + j) * Ccols + c0 + tx];
    __syncthreads();
#pragma unroll
    for (int j = 0; j < 32; j += 8) {
        float x = t[tx][ty + j];
        f16 h, l; split2(x, h, l);
        long o = sOut * blockIdx.z + (long)(c0 + ty + j) * R + r0 + tx;
        ohi[o] = h; olo[o] = l;
    }
}

// ========== plain f16 cast of Wq|Wk|Wv into [qkv][l][in][out] =================
__global__ void __launch_bounds__(256)
split_plain_qkv(const float* __restrict__ Wq, const float* __restrict__ Wk,
                const float* __restrict__ Wv, f16* __restrict__ ohi)
{
    const long DDL = (long)NLAYER * DIM * DIM;
    const long idx = (long)blockIdx.x * blockDim.x + threadIdx.x;
    if (idx >= 3 * DDL) return;
    const int w = (int)(idx / DDL);
    const long r = idx - (long)w * DDL;
    const float* src = (w == 0) ? Wq : (w == 1) ? Wk : Wv;
    ohi[idx] = __float2half_rn(src[r]);
}

// ================ f16 transpose: [R][C] -> [C][R] ==============================
__global__ void __launch_bounds__(256)
transpose_hi(const f16* __restrict__ ihi, f16* __restrict__ ohi,
             int R, int Ccols, long sIn, long sOut)
{
    __shared__ unsigned short t[32][33];
    const int c0 = blockIdx.x * 32, r0 = blockIdx.y * 32;
    const int tx = threadIdx.x & 31, ty = threadIdx.x >> 5;
    const f16* a = ihi + sIn * blockIdx.z;
    f16* o = ohi + sOut * blockIdx.z;
#pragma unroll
    for (int j = 0; j < 32; j += 8)
        t[ty + j][tx] = __half_as_ushort(a[(long)(r0 + ty + j) * Ccols + c0 + tx]);
    __syncthreads();
#pragma unroll
    for (int j = 0; j < 32; j += 8)
        o[(long)(c0 + ty + j) * R + r0 + tx] = __ushort_as_half(t[tx][ty + j]);
}

// ============= fused head bias: b'[l][qkv][a][e] = b_qkv . Wh[l][a][:,e] + bh ==
__global__ void __launch_bounds__(256)
bias_head_kernel(const float* __restrict__ bq, const float* __restrict__ bk,
                 const float* __restrict__ bv, const float* __restrict__ bh,
                 const f16* __restrict__ wht_hi, const f16* __restrict__ wht_lo,
                 float* __restrict__ out)
{
    const int warpId = (blockIdx.x * blockDim.x + threadIdx.x) >> 5;
    const int lane = threadIdx.x & 31;
    const int total = NLAYER * 3 * NHEAD * DHEAD;
    if (warpId >= total) return;
    const int e = warpId & (DHEAD - 1);
    const int a = (warpId / DHEAD) & (NHEAD - 1);
    const int qkv = (warpId / (DHEAD * NHEAD)) % 3;
    const int l = warpId / (DHEAD * NHEAD * 3);
    const float* bsrc = ((qkv == 0) ? bq : (qkv == 1) ? bk : bv) + (long)l * DIM;
    const long wrow = (((long)l * NHEAD + a) * DHEAD + e) * DIM;
    float s = 0.0f;
    for (int i = lane; i < DIM; i += 32)
        s += bsrc[i] * (__half2float(wht_hi[wrow + i]) + __half2float(wht_lo[wrow + i]));
#pragma unroll
    for (int off = 16; off > 0; off >>= 1) s += __shfl_down_sync(0xFFFFFFFFu, s, off);
    if (lane == 0) out[warpId] = s + bh[((long)l * NHEAD + a) * DHEAD + e];
}

// ======== fused prologue misc: copy + f16 cast of hidden =======================
__global__ void __launch_bounds__(256)
prep_misc(const float* __restrict__ hidden, float* __restrict__ h,
          f16* __restrict__ dhi)
{
    const int idx = blockIdx.x * blockDim.x + threadIdx.x;
    if (idx < SEQ * DIM) {
        float v = hidden[idx];
        h[idx] = v;
        dhi[idx] = __float2half_rn(v);
    }
}

// ============ softmax over rows (f16 in, in-place f16 out) =====================
__global__ void __launch_bounds__(256)
softmax_kernel(f16* __restrict__ s16)
{
    const size_t base = (size_t)blockIdx.x * SEQ;
    const int tid = threadIdx.x;

    float v[12];
    float mx = -1e30f;
#pragma unroll
    for (int i = 0; i < 12; i++) {
        v[i] = __half2float(s16[base + tid + i * 256]);
        mx = fmaxf(mx, v[i]);
    }
    __shared__ float red[256];
    red[tid] = mx;
    __syncthreads();
    for (int s = 128; s > 0; s >>= 1) {
        if (tid < s) red[tid] = fmaxf(red[tid], red[tid + s]);
        __syncthreads();
    }
    mx = red[0];
    __syncthreads();

    float sum = 0.0f;
#pragma unroll
    for (int i = 0; i < 12; i++) {
        v[i] = __expf(v[i] - mx);
        sum += v[i];
    }
    red[tid] = sum;
    __syncthreads();
    for (int s = 128; s > 0; s >>= 1) {
        if (tid < s) red[tid] += red[tid + s];
        __syncthreads();
    }
    const float inv = 1.0f / red[0];
#pragma unroll
    for (int i = 0; i < 12; i++)
        s16[base + tid + i * 256] = __float2half_rn(v[i] * inv);
}

// ======================= output heads =======================
__global__ void __launch_bounds__(256)
heads_kernel(const float* __restrict__ h, const float* __restrict__ Whead,
             const float* __restrict__ bhead, const int* __restrict__ nev,
             const int* __restrict__ nag, float* __restrict__ out, int total)
{
    const int warpId = (blockIdx.x * blockDim.x + threadIdx.x) >> 5;
    const int lane = threadIdx.x & 31;
    if (warpId >= total) return;
    const int NEv = *nev;
    const int NAg = *nag;
    int headIdx, token;
    if (warpId < 3 * NAg) {
        headIdx = warpId / NAg;
        token = NEv + warpId % NAg;
    } else {
        headIdx = 3;
        token = warpId - 3 * NAg;
    }
    const float* hr = h + (long)token * DIM;
    const float* w = Whead + (long)headIdx * DIM;
    float s = 0.0f;
    for (int i = lane; i < DIM; i += 32) s = fmaf(hr[i], w[i], s);
#pragma unroll
    for (int off = 16; off > 0; off >>= 1) s += __shfl_down_sync(0xFFFFFFFFu, s, off);
    if (lane == 0) out[warpId] = s + bhead[headIdx];
}

// ======================= host orchestration =======================
#define SMEM128 (3 * (128 * 128 + 16384))
#define SMEM256 (3 * (256 * 128 + 16384))

template <int MT>
static void tcg(const f16* A, int lda, long sAo, long sAi,
                const f16* B, int ldb, long sBo, long sBi,
                const float* bias, long sBias, int nB,
                float* C, f16* Chi, int ldc, long sC,
                int M, int N, int K, int batch, float alpha, int relu,
                int kSplit = 1, float* Cpart = nullptr)
{
    dim3 grid(N / 128, M / MT, batch * kSplit);
    const int smem = (MT == 128) ? SMEM128 : SMEM256;
    mma_gemm<MT><<<grid, 256, smem>>>(A, lda, sAo, sAi, B, ldb, sBo, sBi,
                                      bias, sBias, nB, C, Chi, ldc, sC, K, alpha, relu,
                                      kSplit, Cpart);
}

#define SYM(var, name) cudaGetSymbolAddress((void**)&var, name)

extern "C" void kernel_launch(void* const* d_in, const int* in_sizes, int n_in,
                              void* d_out, int out_size)
{
    const float* hidden = (const float*)d_in[0];
    const float* Wq = (const float*)d_in[1];
    const float* bq = (const float*)d_in[2];
    const float* Wk = (const float*)d_in[3];
    const float* bk = (const float*)d_in[4];
    const float* Wv = (const float*)d_in[5];
    const float* bv = (const float*)d_in[6];
    const float* Wh = (const float*)d_in[7];
    const float* bh = (const float*)d_in[8];
    const float* Wo = (const float*)d_in[9];
    const float* bo = (const float*)d_in[10];
    const float* g1 = (const float*)d_in[11];
    const float* b1n = (const float*)d_in[12];
    const float* g2 = (const float*)d_in[13];
    const float* b2n = (const float*)d_in[14];
    const float* Wf1 = (const float*)d_in[15];
    const float* bf1 = (const float*)d_in[16];
    const float* Wf2 = (const float*)d_in[17];
    const float* bf2 = (const float*)d_in[18];
    const float* Whead = (const float*)d_in[19];
    const float* bhead = (const float*)d_in[20];
    const int* n_events = (const int*)d_in[21];
    const int* n_agents = (const int*)d_in[22];
    (void)in_sizes; (void)n_in;

    cudaFuncSetAttribute(mma_gemm<128>, cudaFuncAttributeMaxDynamicSharedMemorySize, SMEM128);
    cudaFuncSetAttribute(mma_gemm<256>, cudaFuncAttributeMaxDynamicSharedMemorySize, SMEM256);

    float *h, *bprime, *spl;
    SYM(h, g_h); SYM(bprime, g_bprime); SYM(spl, g_split);
    f16 *h_hi, *qkvh, *vht, *ctx, *f1, *at;
    SYM(h_hi, g_h_hi); SYM(qkvh, g_qkvh); SYM(vht, g_vht);
    SYM(ctx, g_ctx); SYM(f1, g_f1); SYM(at, g_at);
    f16 *wsplit, *wpt, *wot, *wht_hi, *wht_lo, *w1t, *w2t;
    SYM(wsplit, g_wsplit); SYM(wpt, g_wpt); SYM(wot, g_wot);
    SYM(wht_hi, g_wht_hi); SYM(wht_lo, g_wht_lo);
    SYM(w1t, g_w1t); SYM(w2t, g_w2t);

    const long DD = (long)DIM * DIM;
    const long SD = (long)SEQ * DIM;
    const long SS = (long)SEQ * SEQ;
    const long SDh = (long)SEQ * DHEAD;
    const long WHL = (long)NHEAD * DHEAD * DIM;
    const long HD = (long)DHEAD * DIM;

    // ---- prologue ----
    transpose_f32_f16<<<dim3(DIM / 32, DIM / 32, NLAYER), 256>>>(Wo, wot, DIM, DIM, DD, DD);
    transpose_split<<<dim3(DHEAD / 32, DIM / 32, NLAYER * NHEAD), 256>>>(
        Wh, wht_hi, wht_lo, DIM, DHEAD, HD, HD);
    transpose_f32_f16<<<dim3(2 * DIM / 32, DIM / 32, NLAYER), 256>>>(Wf1, w1t, DIM, 2 * DIM, 2 * DD, 2 * DD);
    transpose_f32_f16<<<dim3(DIM / 32, 2 * DIM / 32, NLAYER), 256>>>(Wf2, w2t, 2 * DIM, DIM, 2 * DD, 2 * DD);
    {
        const long totalW = 3 * (long)NLAYER * DD;
        split_plain_qkv<<<(int)((totalW + 255) / 256), 256>>>(Wq, Wk, Wv, wsplit);
    }
    prep_misc<<<(SEQ * DIM + 255) / 256, 256>>>(hidden, h, h_hi);
    {
        const int totalB = NLAYER * 3 * NHEAD * DHEAD;
        bias_head_kernel<<<(totalB * 32 + 255) / 256, 256>>>(bq, bk, bv, bh, wht_hi, wht_lo, bprime);
    }
    // W'^T[qkv][l][a] = wht[l][a] (DHEADxDIM) x Wq/k/v  (M=256 -> 128 tile)
    for (int qkv = 0; qkv < 3; qkv++) {
        tcg<128>(wht_hi, DIM, WHL, HD,
                 wsplit + (long)qkv * NLAYER * DD, DIM, DD, 0,
                 nullptr, 0, NHEAD,
                 nullptr, wpt + (long)qkv * NLAYER * WHL,
                 DIM, HD, DHEAD, DIM, DIM, NLAYER * NHEAD, 1.0f, 0);
    }

    const float attn_scale = 1.0f / 16.0f;

    for (int l = 0; l < NLAYER; l++) {
        // fused QKV+head projections: qkvh[qkv][a] = h @ W'[l][qkv][a] + b'
        tcg<256>(h_hi, DIM, 0, 0,
                 wpt + l * WHL, DIM, (long)NLAYER * WHL, HD,
                 bprime + (long)l * 3 * NHEAD * DHEAD, DHEAD, NHEAD,
                 nullptr, qkvh, DHEAD, SDh, SEQ, DHEAD, DIM, 3 * NHEAD, 1.0f, 0);
        // Vh [head][t][e] -> [head][e][t]
        transpose_hi<<<dim3(DHEAD / 32, SEQ / 32, NHEAD), 256>>>(
            qkvh + 2 * SD, vht, SEQ, DHEAD, SDh, SDh);
        // scores = scale * Qh @ Kh^T -> f16
        tcg<256>(qkvh, DHEAD, SDh, 0,
                 qkvh + SD, DHEAD, SDh, 0,
                 nullptr, 0, 1,
                 nullptr, at, SEQ, SS, SEQ, SEQ, DHEAD, NHEAD, attn_scale, 0);
        // softmax in-place
        softmax_kernel<<<NHEAD * SEQ, 256>>>(at);
        // ctx = attn @ Vh  (split-K=3 -> combine to f16 [t][a*DHEAD+e])
        tcg<256>(at, SEQ, SS, 0,
                 vht, SEQ, SDh, 0,
                 nullptr, 0, 1,
                 nullptr, nullptr, 0, 0, SEQ, DHEAD, SEQ, NHEAD, 1.0f, 0,
                 3, spl);
        {
            const long total = (long)NHEAD * SEQ * DHEAD;
            combine_k<<<(int)((total / 4 + 255) / 256), 256>>>(
                spl, SDh, total, DHEAD, 3, nullptr, 0, ctx, DIM, DHEAD);
        }
        // attn_out partials = ctx @ Wo (split-K=4), fused combine+bias+LN
        tcg<256>(ctx, DIM, 0, 0,
                 wot + l * DD, DIM, 0, 0,
                 nullptr, 0, 1,
                 nullptr, nullptr, 0, 0, SEQ, DIM, DIM, 1, 1.0f, 0,
                 4, spl);
        add_ln_combine<<<SEQ, 256>>>(h, spl, 4, bo + (long)l * DIM,
                                     g1 + (long)l * DIM, b1n + (long)l * DIM, h_hi);
        // FFN1: split-K=2, combine does bias+relu -> f16
        tcg<256>(h_hi, DIM, 0, 0,
                 w1t + l * 2 * DD, DIM, 0, 0,
                 nullptr, 0, 1,
                 nullptr, nullptr, 0, 0, SEQ, 2 * DIM, DIM, 1, 1.0f, 0,
                 2, spl);
        combine_k<<<(int)((2 * SD / 4 + 255) / 256), 256>>>(
            spl, 2 * SD, 2 * SD, 2 * DIM, 2, bf1 + (long)l * 2 * DIM, 1, f1, 2 * DIM, 0);
        // FFN2: split-K=4, fused combine+bias+LN
        tcg<256>(f1, 2 * DIM, 0, 0,
                 w2t + l * 2 * DD, 2 * DIM, 0, 0,
                 nullptr, 0, 1,
                 nullptr, nullptr, 0, 0, SEQ, DIM, 2 * DIM, 1, 1.0f, 0,
                 4, spl);
        add_ln_combine<<<SEQ, 256>>>(h, spl, 4, bf2 + (long)l * DIM,
                                     g2 + (long)l * DIM, b2n + (long)l * DIM, h_hi);
    }

    const int blocks = (out_size * 32 + 255) / 256;
    heads_kernel<<<blocks, 256>>>(h, Whead, bhead, n_events, n_agents, (float*)d_out, out_size);
}

// round 16
// speedup vs baseline: 1.3764x; 1.0155x over previous
#include <cuda_runtime.h>
#include <cuda_fp16.h>
#include <cstdint>
#include <math.h>

#define SEQ 3072
#define DIM 1024
#define NHEAD 4
#define DHEAD 256
#define NLAYER 4
#define LN_EPS 1e-5f
typedef __half f16;

// ======================= scratch (static device arrays) =======================
__device__ float g_h[SEQ * DIM];
__device__ f16 g_split[4 * SEQ * DIM];                               // split-K partials (f16)

__device__ f16 g_h_hi[SEQ * DIM];
__device__ f16 g_qkvh[3 * SEQ * DIM];                                // [qkv][head][t][e]
__device__ f16 g_vht[SEQ * DIM];                                     // [head][e][t]
__device__ f16 g_ctx[SEQ * DIM];                                     // [t][head*DHEAD+e]
__device__ f16 g_f1[SEQ * 2 * DIM];
__device__ f16 g_at[(size_t)NHEAD * SEQ * SEQ];                      // scores/attn

// weights
__device__ f16 g_wsplit[3 * NLAYER * DIM * DIM];                     // [qkv][l][in][out]
__device__ f16 g_wpt[3 * NLAYER * NHEAD * DHEAD * DIM];              // W'^T [qkv][l][a][e][in]
__device__ f16 g_wot[NLAYER * DIM * DIM];
__device__ f16 g_wht_hi[NLAYER * NHEAD * DHEAD * DIM], g_wht_lo[NLAYER * NHEAD * DHEAD * DIM];
__device__ f16 g_w1t[NLAYER * DIM * 2 * DIM];
__device__ f16 g_w2t[NLAYER * 2 * DIM * DIM];
__device__ float g_bprime[NLAYER * 3 * NHEAD * DHEAD];               // [l][qkv][a][e]

// ======================= helpers =======================
__device__ __forceinline__ uint32_t s2u(const void* p) {
    uint32_t a;
    asm("{ .reg .u64 t; cvta.to.shared.u64 t, %1; cvt.u32.u64 %0, t; }" : "=r"(a) : "l"(p));
    return a;
}
__device__ __forceinline__ void split2(float x, f16& h, f16& l) {
    h = __float2half_rn(x);
    l = __float2half_rn(x - __half2float(h));
}
__device__ __forceinline__ void cp16(uint32_t dst, const void* src) {
    asm volatile("cp.async.cg.shared.global [%0], [%1], 16;" :: "r"(dst), "l"(src) : "memory");
}
#define CP_COMMIT() asm volatile("cp.async.commit_group;" ::: "memory")
#define CP_WAIT(n)  asm volatile("cp.async.wait_group %0;" :: "n"(n) : "memory")

__device__ __forceinline__ void ldm_x4(uint32_t* r, uint32_t addr) {
    asm volatile("ldmatrix.sync.aligned.m8n8.x4.shared.b16 {%0,%1,%2,%3}, [%4];"
                 : "=r"(r[0]), "=r"(r[1]), "=r"(r[2]), "=r"(r[3]) : "r"(addr));
}
__device__ __forceinline__ void mma_f16(float* c, const uint32_t* a, const uint32_t* b) {
    asm volatile(
        "mma.sync.aligned.m16n8k16.row.col.f32.f16.f16.f32 "
        "{%0,%1,%2,%3}, {%4,%5,%6,%7}, {%8,%9}, {%0,%1,%2,%3};"
        : "+f"(c[0]), "+f"(c[1]), "+f"(c[2]), "+f"(c[3])
        : "r"(a[0]), "r"(a[1]), "r"(a[2]), "r"(a[3]), "r"(b[0]), "r"(b[1]));
}
__device__ __forceinline__ uint32_t pack2(float x0, float x1) {
    return (uint32_t)__half_as_ushort(__float2half_rn(x0)) |
           ((uint32_t)__half_as_ushort(__float2half_rn(x1)) << 16);
}

// ======================= fp16 mma.sync GEMM (templated M-tile) =================
// C[m][n] = alpha * sum_k A[m][k]*B[n][k] + bias[n]   (A, B fp16; f32 accum)
// CTA tile MT x 128, BK=64, 3-stage cp.async, SW128, occ 1.
// MT=128: 2x4 warps of 64x32.  MT=256: 4x2 warps of 64x64.
// Optional split-K: grid.z = batch*kSplit; f16 partials Cpart[(zs*nzb+zb)*M*Npart+...].
template <int MT>
__global__ void __launch_bounds__(256, 1)
mma_gemm(const f16* __restrict__ A, int lda, long sAo, long sAi,
         const f16* __restrict__ B, int ldb, long sBo, long sBi,
         const float* __restrict__ bias, long sBias, int nB,
         float* __restrict__ C, f16* __restrict__ Chi,
         int ldc, long sC, int K, float alpha, int relu,
         int kSplit, f16* __restrict__ Cpart)
{
    constexpr int MW = MT / 64;
    constexpr int NW = 8 / MW;
    constexpr int WN = 128 / NW;
    constexpr int NT = WN / 8;
    constexpr uint32_t ABYTES = MT * 128;
    constexpr uint32_t STG = ABYTES + 16384;
    constexpr int AUNITS = MT * 8;
    constexpr int UNITS = AUNITS + 1024;

    extern __shared__ char sm[];
    const uint32_t sb = s2u(sm);
    const int tid = threadIdx.x;
    const int wid = tid >> 5;
    const int lane = tid & 31;
    const int wm = wid / NW;
    const int wn = wid % NW;
    int zb = blockIdx.z;
    int zs = 0;
    if (kSplit > 1) { zs = zb % kSplit; zb /= kSplit; }
    const int zo = zb / nB;
    const int zi = zb - zo * nB;
    const long row0 = (long)blockIdx.y * MT;
    const long col0 = (long)blockIdx.x * 128;

    const int Ksub = K / kSplit;
    const long koff = (long)zs * Ksub;

    A += zo * sAo + zi * sAi + koff;
    B += zo * sBo + zi * sBi + koff;

    const int nch = Ksub >> 6;

    auto load_chunk = [&](int ch, int stage) {
        const long k0 = (long)ch << 6;
#pragma unroll
        for (int i = 0; i < UNITS / 256; i++) {
            const int u = tid + (i << 8);
            const f16* p;
            uint32_t base;
            int q;
            if (u < AUNITS) {
                q = u;
                p = A + (row0 + (q >> 3)) * lda;
                base = 0;
            } else {
                q = u - AUNITS;
                p = B + (col0 + (q >> 3)) * ldb;
                base = ABYTES;
            }
            const int sg = (q & 7) << 3;
            uint32_t off = (uint32_t)(q << 4);
            off ^= (off >> 3) & 0x70;
            cp16(sb + (uint32_t)stage * STG + base + off, p + k0 + sg);
        }
        CP_COMMIT();
    };

    float acc[4][NT][4];
#pragma unroll
    for (int a = 0; a < 4; a++)
#pragma unroll
        for (int b = 0; b < NT; b++)
#pragma unroll
            for (int c = 0; c < 4; c++) acc[a][b][c] = 0.0f;

    load_chunk(0, 0);
    load_chunk(1, 1);

    for (int ch = 0; ch < nch; ch++) {
        if (ch + 2 < nch) {
            load_chunk(ch + 2, (ch + 2) % 3);
            CP_WAIT(2);
        } else {
            CP_WAIT(0);
        }
        __syncthreads();

        const uint32_t stg = sb + (uint32_t)(ch % 3) * STG;

#pragma unroll
        for (int ks = 0; ks < 4; ks++) {
            uint32_t ah[4][4], bh[NT / 2][4];
#pragma unroll
            for (int mt = 0; mt < 4; mt++) {
                const int row = wm * 64 + mt * 16 + (lane & 15);
                const int colb = ks * 32 + ((lane >> 4) << 4);
                uint32_t off = (uint32_t)(row * 128 + colb);
                off ^= (off >> 3) & 0x70;
                ldm_x4(ah[mt], stg + off);
            }
#pragma unroll
            for (int nb = 0; nb < NT / 2; nb++) {
                const int row = wn * WN + nb * 16 + (lane & 7) + ((lane >> 4) << 3);
                const int colb = ks * 32 + (((lane >> 3) & 1) << 4);
                uint32_t off = (uint32_t)(row * 128 + colb);
                off ^= (off >> 3) & 0x70;
                ldm_x4(bh[nb], stg + ABYTES + off);
            }
#pragma unroll
            for (int mt = 0; mt < 4; mt++)
#pragma unroll
                for (int nt = 0; nt < NT; nt++) {
                    const uint32_t* bhp = &bh[nt >> 1][(nt & 1) * 2];
                    mma_f16(acc[mt][nt], ah[mt], bhp);
                }
        }
        __syncthreads();
    }

    // -------- epilogue --------
    if (kSplit > 1) {
        const long Npart = (long)gridDim.x * 128;
        const long Mtot = (long)gridDim.y * MT;
        const int nzb = gridDim.z / kSplit;
        f16* dst = Cpart + ((long)zs * nzb + zb) * Mtot * Npart;
#pragma unroll
        for (int mt = 0; mt < 4; mt++)
#pragma unroll
            for (int nt = 0; nt < NT; nt++) {
                float* d = acc[mt][nt];
                const long gm = row0 + wm * 64 + mt * 16 + (lane >> 2);
                const long gn = col0 + wn * WN + nt * 8 + (lane & 3) * 2;
#pragma unroll
                for (int half = 0; half < 2; half++) {
                    const long r = gm + half * 8;
                    *(uint32_t*)(dst + r * Npart + gn) =
                        pack2(d[half * 2 + 0] * alpha, d[half * 2 + 1] * alpha);
                }
            }
        return;
    }

    float* Cz = C ? C + sC * zb : nullptr;
    f16* Hz = Chi ? Chi + sC * zb : nullptr;
    const float* bz = bias ? bias + (long)zb * sBias : nullptr;

#pragma unroll
    for (int mt = 0; mt < 4; mt++)
#pragma unroll
        for (int nt = 0; nt < NT; nt++) {
            float* d = acc[mt][nt];
            const long gm = row0 + wm * 64 + mt * 16 + (lane >> 2);
            const long gn = col0 + wn * WN + nt * 8 + (lane & 3) * 2;
            float b0 = 0.0f, b1 = 0.0f;
            if (bz) { b0 = __ldg(bz + gn); b1 = __ldg(bz + gn + 1); }
#pragma unroll
            for (int half = 0; half < 2; half++) {
                const long r = gm + half * 8;
                float x0 = d[half * 2 + 0] * alpha + b0;
                float x1 = d[half * 2 + 1] * alpha + b1;
                if (relu) { x0 = fmaxf(x0, 0.0f); x1 = fmaxf(x1, 0.0f); }
                const long o = r * ldc + gn;
                if (Cz) *(float2*)(Cz + o) = make_float2(x0, x1);
                if (Hz) *(uint32_t*)(Hz + o) = pack2(x0, x1);
            }
        }
}

// =============== split-K combine: out = sum_s p_s (+bias, relu) -> f16 =========
__global__ void __launch_bounds__(256)
combine_k(const f16* __restrict__ part, long perMat, long total, int Npart,
          int kSplit, const float* __restrict__ bias, int relu,
          f16* __restrict__ outH, int ldc, long sC)
{
    const long i = ((long)blockIdx.x * blockDim.x + threadIdx.x) * 4;
    if (i >= total) return;
    const long zb = i / perMat;
    const long rem = i - zb * perMat;
    const long m = rem / Npart;
    const int n = (int)(rem - m * Npart);
    float x0 = 0.0f, x1 = 0.0f, x2 = 0.0f, x3 = 0.0f;
    for (int s = 0; s < kSplit; s++) {
        const uint2 pv = *(const uint2*)(part + (long)s * total + i);
        float2 a = __half22float2(*(const __half2*)&pv.x);
        float2 b = __half22float2(*(const __half2*)&pv.y);
        x0 += a.x; x1 += a.y; x2 += b.x; x3 += b.y;
    }
    if (bias) {
        x0 += __ldg(bias + n); x1 += __ldg(bias + n + 1);
        x2 += __ldg(bias + n + 2); x3 += __ldg(bias + n + 3);
    }
    if (relu) {
        x0 = fmaxf(x0, 0.0f); x1 = fmaxf(x1, 0.0f);
        x2 = fmaxf(x2, 0.0f); x3 = fmaxf(x3, 0.0f);
    }
    const long o = zb * sC + m * ldc + n;
    uint2 wh;
    wh.x = pack2(x0, x1);
    wh.y = pack2(x2, x3);
    *(uint2*)(outH + o) = wh;
}

// ====== fused: h = LayerNorm(h + (sum_s p_s + bias)) * g + b, f32 + f16 ========
__global__ void __launch_bounds__(256)
add_ln_combine(float* __restrict__ h, const f16* __restrict__ part, int kSplit,
               const float* __restrict__ bias,
               const float* __restrict__ g, const float* __restrict__ b,
               f16* __restrict__ ohi)
{
    const long row = blockIdx.x;
    float* hp = h + row * (long)DIM;
    const int tid = threadIdx.x;

    float v[4];
    float sum = 0.0f;
#pragma unroll
    for (int i = 0; i < 4; i++) {
        const int c = tid + i * 256;
        float acc = bias[c];
        for (int s = 0; s < kSplit; s++)
            acc += __half2float(part[(long)s * SEQ * DIM + row * (long)DIM + c]);
        v[i] = hp[c] + acc;
        sum += v[i];
    }
    __shared__ float red[256];
    red[tid] = sum;
    __syncthreads();
    for (int s = 128; s > 0; s >>= 1) {
        if (tid < s) red[tid] += red[tid + s];
        __syncthreads();
    }
    const float mu = red[0] * (1.0f / DIM);
    __syncthreads();

    float vs = 0.0f;
#pragma unroll
    for (int i = 0; i < 4; i++) {
        const float d = v[i] - mu;
        vs += d * d;
    }
    red[tid] = vs;
    __syncthreads();
    for (int s = 128; s > 0; s >>= 1) {
        if (tid < s) red[tid] += red[tid + s];
        __syncthreads();
    }
    const float inv = rsqrtf(red[0] * (1.0f / DIM) + LN_EPS);
    __syncthreads();
#pragma unroll
    for (int i = 0; i < 4; i++) {
        const int c = tid + i * 256;
        float y = g[c] * (v[i] - mu) * inv + b[c];
        hp[c] = y;
        ohi[row * (long)DIM + c] = __float2half_rn(y);
    }
}

// ============= transpose f32 -> f16 (hi only): [R][C] -> [C][R] ================
__global__ void __launch_bounds__(256)
transpose_f32_f16(const float* __restrict__ in, f16* __restrict__ ohi,
                  int R, int Ccols, long sIn, long sOut)
{
    __shared__ float t[32][33];
    const float* ip = in + sIn * blockIdx.z;
    const int c0 = blockIdx.x * 32, r0 = blockIdx.y * 32;
    const int tx = threadIdx.x & 31, ty = threadIdx.x >> 5;
#pragma unroll
    for (int j = 0; j < 32; j += 8)
        t[ty + j][tx] = ip[(long)(r0 + ty + j) * Ccols + c0 + tx];
    __syncthreads();
#pragma unroll
    for (int j = 0; j < 32; j += 8) {
        long o = sOut * blockIdx.z + (long)(c0 + ty + j) * R + r0 + tx;
        ohi[o] = __float2half_rn(t[tx][ty + j]);
    }
}

// ============= transpose f32 -> f16 hi/lo: [R][C] -> [C][R] (for Wh) ===========
__global__ void __launch_bounds__(256)
transpose_split(const float* __restrict__ in, f16* __restrict__ ohi, f16* __restrict__ olo,
                int R, int Ccols, long sIn, long sOut)
{
    __shared__ float t[32][33];
    const float* ip = in + sIn * blockIdx.z;
    const int c0 = blockIdx.x * 32, r0 = blockIdx.y * 32;
    const int tx = threadIdx.x & 31, ty = threadIdx.x >> 5;
#pragma unroll
    for (int j = 0; j < 32; j += 8)
        t[ty + j][tx] = ip[(long)(r0 + ty + j) * Ccols + c0 + tx];
    __syncthreads();
#pragma unroll
    for (int j = 0; j < 32; j += 8) {
        float x = t[tx][ty + j];
        f16 h, l; split2(x, h, l);
        long o = sOut * blockIdx.z + (long)(c0 + ty + j) * R + r0 + tx;
        ohi[o] = h; olo[o] = l;
    }
}

// ========== plain f16 cast of Wq|Wk|Wv into [qkv][l][in][out] =================
__global__ void __launch_bounds__(256)
split_plain_qkv(const float* __restrict__ Wq, const float* __restrict__ Wk,
                const float* __restrict__ Wv, f16* __restrict__ ohi)
{
    const long DDL = (long)NLAYER * DIM * DIM;
    const long idx = (long)blockIdx.x * blockDim.x + threadIdx.x;
    if (idx >= 3 * DDL) return;
    const int w = (int)(idx / DDL);
    const long r = idx - (long)w * DDL;
    const float* src = (w == 0) ? Wq : (w == 1) ? Wk : Wv;
    ohi[idx] = __float2half_rn(src[r]);
}

// ================ f16 transpose: [R][C] -> [C][R] ==============================
__global__ void __launch_bounds__(256)
transpose_hi(const f16* __restrict__ ihi, f16* __restrict__ ohi,
             int R, int Ccols, long sIn, long sOut)
{
    __shared__ unsigned short t[32][33];
    const int c0 = blockIdx.x * 32, r0 = blockIdx.y * 32;
    const int tx = threadIdx.x & 31, ty = threadIdx.x >> 5;
    const f16* a = ihi + sIn * blockIdx.z;
    f16* o = ohi + sOut * blockIdx.z;
#pragma unroll
    for (int j = 0; j < 32; j += 8)
        t[ty + j][tx] = __half_as_ushort(a[(long)(r0 + ty + j) * Ccols + c0 + tx]);
    __syncthreads();
#pragma unroll
    for (int j = 0; j < 32; j += 8)
        o[(long)(c0 + ty + j) * R + r0 + tx] = __ushort_as_half(t[tx][ty + j]);
}

// ============= fused head bias: b'[l][qkv][a][e] = b_qkv . Wh[l][a][:,e] + bh ==
__global__ void __launch_bounds__(256)
bias_head_kernel(const float* __restrict__ bq, const float* __restrict__ bk,
                 const float* __restrict__ bv, const float* __restrict__ bh,
                 const f16* __restrict__ wht_hi, const f16* __restrict__ wht_lo,
                 float* __restrict__ out)
{
    const int warpId = (blockIdx.x * blockDim.x + threadIdx.x) >> 5;
    const int lane = threadIdx.x & 31;
    const int total = NLAYER * 3 * NHEAD * DHEAD;
    if (warpId >= total) return;
    const int e = warpId & (DHEAD - 1);
    const int a = (warpId / DHEAD) & (NHEAD - 1);
    const int qkv = (warpId / (DHEAD * NHEAD)) % 3;
    const int l = warpId / (DHEAD * NHEAD * 3);
    const float* bsrc = ((qkv == 0) ? bq : (qkv == 1) ? bk : bv) + (long)l * DIM;
    const long wrow = (((long)l * NHEAD + a) * DHEAD + e) * DIM;
    float s = 0.0f;
    for (int i = lane; i < DIM; i += 32)
        s += bsrc[i] * (__half2float(wht_hi[wrow + i]) + __half2float(wht_lo[wrow + i]));
#pragma unroll
    for (int off = 16; off > 0; off >>= 1) s += __shfl_down_sync(0xFFFFFFFFu, s, off);
    if (lane == 0) out[warpId] = s + bh[((long)l * NHEAD + a) * DHEAD + e];
}

// ======== fused prologue misc: copy + f16 cast of hidden =======================
__global__ void __launch_bounds__(256)
prep_misc(const float* __restrict__ hidden, float* __restrict__ h,
          f16* __restrict__ dhi)
{
    const int idx = blockIdx.x * blockDim.x + threadIdx.x;
    if (idx < SEQ * DIM) {
        float v = hidden[idx];
        h[idx] = v;
        dhi[idx] = __float2half_rn(v);
    }
}

// ============ softmax over rows (half2-vectorized, in-place) ===================
__global__ void __launch_bounds__(256)
softmax_kernel(f16* __restrict__ s16)
{
    const size_t base = (size_t)blockIdx.x * SEQ;
    __half2* p = (__half2*)(s16 + base);      // 1536 half2 per row
    const int tid = threadIdx.x;

    float2 v[6];
    float mx = -1e30f;
#pragma unroll
    for (int i = 0; i < 6; i++) {
        v[i] = __half22float2(p[tid + i * 256]);
        mx = fmaxf(mx, fmaxf(v[i].x, v[i].y));
    }
    __shared__ float red[256];
    red[tid] = mx;
    __syncthreads();
    for (int s = 128; s > 0; s >>= 1) {
        if (tid < s) red[tid] = fmaxf(red[tid], red[tid + s]);
        __syncthreads();
    }
    mx = red[0];
    __syncthreads();

    float sum = 0.0f;
#pragma unroll
    for (int i = 0; i < 6; i++) {
        v[i].x = __expf(v[i].x - mx);
        v[i].y = __expf(v[i].y - mx);
        sum += v[i].x + v[i].y;
    }
    red[tid] = sum;
    __syncthreads();
    for (int s = 128; s > 0; s >>= 1) {
        if (tid < s) red[tid] += red[tid + s];
        __syncthreads();
    }
    const float inv = 1.0f / red[0];
#pragma unroll
    for (int i = 0; i < 6; i++)
        p[tid + i * 256] = __floats2half2_rn(v[i].x * inv, v[i].y * inv);
}

// ======================= output heads =======================
__global__ void __launch_bounds__(256)
heads_kernel(const float* __restrict__ h, const float* __restrict__ Whead,
             const float* __restrict__ bhead, const int* __restrict__ nev,
             const int* __restrict__ nag, float* __restrict__ out, int total)
{
    const int warpId = (blockIdx.x * blockDim.x + threadIdx.x) >> 5;
    const int lane = threadIdx.x & 31;
    if (warpId >= total) return;
    const int NEv = *nev;
    const int NAg = *nag;
    int headIdx, token;
    if (warpId < 3 * NAg) {
        headIdx = warpId / NAg;
        token = NEv + warpId % NAg;
    } else {
        headIdx = 3;
        token = warpId - 3 * NAg;
    }
    const float* hr = h + (long)token * DIM;
    const float* w = Whead + (long)headIdx * DIM;
    float s = 0.0f;
    for (int i = lane; i < DIM; i += 32) s = fmaf(hr[i], w[i], s);
#pragma unroll
    for (int off = 16; off > 0; off >>= 1) s += __shfl_down_sync(0xFFFFFFFFu, s, off);
    if (lane == 0) out[warpId] = s + bhead[headIdx];
}

// ======================= host orchestration =======================
#define SMEM128 (3 * (128 * 128 + 16384))
#define SMEM256 (3 * (256 * 128 + 16384))

template <int MT>
static void tcg(const f16* A, int lda, long sAo, long sAi,
                const f16* B, int ldb, long sBo, long sBi,
                const float* bias, long sBias, int nB,
                float* C, f16* Chi, int ldc, long sC,
                int M, int N, int K, int batch, float alpha, int relu,
                int kSplit = 1, f16* Cpart = nullptr)
{
    dim3 grid(N / 128, M / MT, batch * kSplit);
    const int smem = (MT == 128) ? SMEM128 : SMEM256;
    mma_gemm<MT><<<grid, 256, smem>>>(A, lda, sAo, sAi, B, ldb, sBo, sBi,
                                      bias, sBias, nB, C, Chi, ldc, sC, K, alpha, relu,
                                      kSplit, Cpart);
}

#define SYM(var, name) cudaGetSymbolAddress((void**)&var, name)

extern "C" void kernel_launch(void* const* d_in, const int* in_sizes, int n_in,
                              void* d_out, int out_size)
{
    const float* hidden = (const float*)d_in[0];
    const float* Wq = (const float*)d_in[1];
    const float* bq = (const float*)d_in[2];
    const float* Wk = (const float*)d_in[3];
    const float* bk = (const float*)d_in[4];
    const float* Wv = (const float*)d_in[5];
    const float* bv = (const float*)d_in[6];
    const float* Wh = (const float*)d_in[7];
    const float* bh = (const float*)d_in[8];
    const float* Wo = (const float*)d_in[9];
    const float* bo = (const float*)d_in[10];
    const float* g1 = (const float*)d_in[11];
    const float* b1n = (const float*)d_in[12];
    const float* g2 = (const float*)d_in[13];
    const float* b2n = (const float*)d_in[14];
    const float* Wf1 = (const float*)d_in[15];
    const float* bf1 = (const float*)d_in[16];
    const float* Wf2 = (const float*)d_in[17];
    const float* bf2 = (const float*)d_in[18];
    const float* Whead = (const float*)d_in[19];
    const float* bhead = (const float*)d_in[20];
    const int* n_events = (const int*)d_in[21];
    const int* n_agents = (const int*)d_in[22];
    (void)in_sizes; (void)n_in;

    cudaFuncSetAttribute(mma_gemm<128>, cudaFuncAttributeMaxDynamicSharedMemorySize, SMEM128);
    cudaFuncSetAttribute(mma_gemm<256>, cudaFuncAttributeMaxDynamicSharedMemorySize, SMEM256);

    float *h, *bprime;
    f16 *spl;
    SYM(h, g_h); SYM(bprime, g_bprime); SYM(spl, g_split);
    f16 *h_hi, *qkvh, *vht, *ctx, *f1, *at;
    SYM(h_hi, g_h_hi); SYM(qkvh, g_qkvh); SYM(vht, g_vht);
    SYM(ctx, g_ctx); SYM(f1, g_f1); SYM(at, g_at);
    f16 *wsplit, *wpt, *wot, *wht_hi, *wht_lo, *w1t, *w2t;
    SYM(wsplit, g_wsplit); SYM(wpt, g_wpt); SYM(wot, g_wot);
    SYM(wht_hi, g_wht_hi); SYM(wht_lo, g_wht_lo);
    SYM(w1t, g_w1t); SYM(w2t, g_w2t);

    const long DD = (long)DIM * DIM;
    const long SD = (long)SEQ * DIM;
    const long SS = (long)SEQ * SEQ;
    const long SDh = (long)SEQ * DHEAD;
    const long WHL = (long)NHEAD * DHEAD * DIM;
    const long HD = (long)DHEAD * DIM;

    // ---- prologue ----
    transpose_f32_f16<<<dim3(DIM / 32, DIM / 32, NLAYER), 256>>>(Wo, wot, DIM, DIM, DD, DD);
    transpose_split<<<dim3(DHEAD / 32, DIM / 32, NLAYER * NHEAD), 256>>>(
        Wh, wht_hi, wht_lo, DIM, DHEAD, HD, HD);
    transpose_f32_f16<<<dim3(2 * DIM / 32, DIM / 32, NLAYER), 256>>>(Wf1, w1t, DIM, 2 * DIM, 2 * DD, 2 * DD);
    transpose_f32_f16<<<dim3(DIM / 32, 2 * DIM / 32, NLAYER), 256>>>(Wf2, w2t, 2 * DIM, DIM, 2 * DD, 2 * DD);
    {
        const long totalW = 3 * (long)NLAYER * DD;
        split_plain_qkv<<<(int)((totalW + 255) / 256), 256>>>(Wq, Wk, Wv, wsplit);
    }
    prep_misc<<<(SEQ * DIM + 255) / 256, 256>>>(hidden, h, h_hi);
    {
        const int totalB = NLAYER * 3 * NHEAD * DHEAD;
        bias_head_kernel<<<(totalB * 32 + 255) / 256, 256>>>(bq, bk, bv, bh, wht_hi, wht_lo, bprime);
    }
    // W'^T[qkv][l][a] = wht[l][a] (DHEADxDIM) x Wq/k/v
    for (int qkv = 0; qkv < 3; qkv++) {
        tcg<128>(wht_hi, DIM, WHL, HD,
                 wsplit + (long)qkv * NLAYER * DD, DIM, DD, 0,
                 nullptr, 0, NHEAD,
                 nullptr, wpt + (long)qkv * NLAYER * WHL,
                 DIM, HD, DHEAD, DIM, DIM, NLAYER * NHEAD, 1.0f, 0);
    }

    const float attn_scale = 1.0f / 16.0f;

    for (int l = 0; l < NLAYER; l++) {
        // fused QKV+head projections: qkvh[qkv][a] = h @ W'[l][qkv][a] + b'
        tcg<256>(h_hi, DIM, 0, 0,
                 wpt + l * WHL, DIM, (long)NLAYER * WHL, HD,
                 bprime + (long)l * 3 * NHEAD * DHEAD, DHEAD, NHEAD,
                 nullptr, qkvh, DHEAD, SDh, SEQ, DHEAD, DIM, 3 * NHEAD, 1.0f, 0);
        // Vh [head][t][e] -> [head][e][t]
        transpose_hi<<<dim3(DHEAD / 32, SEQ / 32, NHEAD), 256>>>(
            qkvh + 2 * SD, vht, SEQ, DHEAD, SDh, SDh);
        // scores = scale * Qh @ Kh^T -> f16
        tcg<256>(qkvh, DHEAD, SDh, 0,
                 qkvh + SD, DHEAD, SDh, 0,
                 nullptr, 0, 1,
                 nullptr, at, SEQ, SS, SEQ, SEQ, DHEAD, NHEAD, attn_scale, 0);
        // softmax in-place
        softmax_kernel<<<NHEAD * SEQ, 256>>>(at);
        // ctx = attn @ Vh  (split-K=3 -> combine to f16 [t][a*DHEAD+e])
        tcg<256>(at, SEQ, SS, 0,
                 vht, SEQ, SDh, 0,
                 nullptr, 0, 1,
                 nullptr, nullptr, 0, 0, SEQ, DHEAD, SEQ, NHEAD, 1.0f, 0,
                 3, spl);
        {
            const long total = (long)NHEAD * SEQ * DHEAD;
            combine_k<<<(int)((total / 4 + 255) / 256), 256>>>(
                spl, SDh, total, DHEAD, 3, nullptr, 0, ctx, DIM, DHEAD);
        }
        // attn_out partials = ctx @ Wo (split-K=4), fused combine+bias+LN
        tcg<256>(ctx, DIM, 0, 0,
                 wot + l * DD, DIM, 0, 0,
                 nullptr, 0, 1,
                 nullptr, nullptr, 0, 0, SEQ, DIM, DIM, 1, 1.0f, 0,
                 4, spl);
        add_ln_combine<<<SEQ, 256>>>(h, spl, 4, bo + (long)l * DIM,
                                     g1 + (long)l * DIM, b1n + (long)l * DIM, h_hi);
        // FFN1: split-K=2, combine does bias+relu -> f16
        tcg<256>(h_hi, DIM, 0, 0,
                 w1t + l * 2 * DD, DIM, 0, 0,
                 nullptr, 0, 1,
                 nullptr, nullptr, 0, 0, SEQ, 2 * DIM, DIM, 1, 1.0f, 0,
                 2, spl);
        combine_k<<<(int)((2 * SD / 4 + 255) / 256), 256>>>(
            spl, 2 * SD, 2 * SD, 2 * DIM, 2, bf1 + (long)l * 2 * DIM, 1, f1, 2 * DIM, 0);
        // FFN2: split-K=4, fused combine+bias+LN
        tcg<256>(f1, 2 * DIM, 0, 0,
                 w2t + l * 2 * DD, 2 * DIM, 0, 0,
                 nullptr, 0, 1,
                 nullptr, nullptr, 0, 0, SEQ, DIM, 2 * DIM, 1, 1.0f, 0,
                 4, spl);
        add_ln_combine<<<SEQ, 256>>>(h, spl, 4, bf2 + (long)l * DIM,
                                     g2 + (long)l * DIM, b2n + (long)l * DIM, h_hi);
    }

    const int blocks = (out_size * 32 + 255) / 256;
    heads_kernel<<<blocks, 256>>>(h, Whead, bhead, n_events, n_agents, (float*)d_out, out_size);
}

// round 17
// speedup vs baseline: 1.4219x; 1.0331x over previous
#include <cuda_runtime.h>
#include <cuda_fp16.h>
#include <cstdint>
#include <math.h>

#define SEQ 3072
#define DIM 1024
#define NHEAD 4
#define DHEAD 256
#define NLAYER 4
#define LN_EPS 1e-5f
typedef __half f16;

// ======================= scratch (static device arrays) =======================
__device__ float g_h[SEQ * DIM];
__device__ f16 g_split[4 * SEQ * DIM];                               // split-K partials (f16)

__device__ f16 g_h_hi[SEQ * DIM];
__device__ f16 g_qkvh[3 * SEQ * DIM];                                // [qkv][head][t][e]
__device__ f16 g_vht[SEQ * DIM];                                     // [head][e][t]
__device__ f16 g_ctx[SEQ * DIM];                                     // [t][head*DHEAD+e]
__device__ f16 g_f1[SEQ * 2 * DIM];
__device__ f16 g_at[(size_t)NHEAD * SEQ * SEQ];                      // scores/attn

// weights
__device__ f16 g_wsplit[3 * NLAYER * DIM * DIM];                     // [qkv][l][in][out]
__device__ f16 g_wpt[3 * NLAYER * NHEAD * DHEAD * DIM];              // W'^T [qkv][l][a][e][in]
__device__ f16 g_wot[NLAYER * DIM * DIM];
__device__ f16 g_wht_hi[NLAYER * NHEAD * DHEAD * DIM], g_wht_lo[NLAYER * NHEAD * DHEAD * DIM];
__device__ f16 g_w1t[NLAYER * DIM * 2 * DIM];
__device__ f16 g_w2t[NLAYER * 2 * DIM * DIM];
__device__ float g_bprime[NLAYER * 3 * NHEAD * DHEAD];               // [l][qkv][a][e]

// ======================= helpers =======================
__device__ __forceinline__ uint32_t s2u(const void* p) {
    uint32_t a;
    asm("{ .reg .u64 t; cvta.to.shared.u64 t, %1; cvt.u32.u64 %0, t; }" : "=r"(a) : "l"(p));
    return a;
}
__device__ __forceinline__ void split2(float x, f16& h, f16& l) {
    h = __float2half_rn(x);
    l = __float2half_rn(x - __half2float(h));
}
__device__ __forceinline__ void cp16(uint32_t dst, const void* src) {
    asm volatile("cp.async.cg.shared.global [%0], [%1], 16;" :: "r"(dst), "l"(src) : "memory");
}
#define CP_COMMIT() asm volatile("cp.async.commit_group;" ::: "memory")
#define CP_WAIT(n)  asm volatile("cp.async.wait_group %0;" :: "n"(n) : "memory")

__device__ __forceinline__ void ldm_x4(uint32_t* r, uint32_t addr) {
    asm volatile("ldmatrix.sync.aligned.m8n8.x4.shared.b16 {%0,%1,%2,%3}, [%4];"
                 : "=r"(r[0]), "=r"(r[1]), "=r"(r[2]), "=r"(r[3]) : "r"(addr));
}
__device__ __forceinline__ void mma_f16(float* c, const uint32_t* a, const uint32_t* b) {
    asm volatile(
        "mma.sync.aligned.m16n8k16.row.col.f32.f16.f16.f32 "
        "{%0,%1,%2,%3}, {%4,%5,%6,%7}, {%8,%9}, {%0,%1,%2,%3};"
        : "+f"(c[0]), "+f"(c[1]), "+f"(c[2]), "+f"(c[3])
        : "r"(a[0]), "r"(a[1]), "r"(a[2]), "r"(a[3]), "r"(b[0]), "r"(b[1]));
}
__device__ __forceinline__ uint32_t pack2(float x0, float x1) {
    return (uint32_t)__half_as_ushort(__float2half_rn(x0)) |
           ((uint32_t)__half_as_ushort(__float2half_rn(x1)) << 16);
}

// ======================= fp16 mma.sync GEMM (templated M-tile) =================
// C[m][n] = alpha * sum_k A[m][k]*B[n][k] + bias[n]   (A, B fp16; f32 accum)
// CTA tile MT x 128, BK=64, 3-stage cp.async, SW128, occ 1.
// MT=128: 2x4 warps of 64x32.  MT=256: 4x2 warps of 64x64.
// Optional split-K: grid.z = batch*kSplit; f16 partials Cpart[(zs*nzb+zb)*M*Npart+...].
template <int MT>
__global__ void __launch_bounds__(256, 1)
mma_gemm(const f16* __restrict__ A, int lda, long sAo, long sAi,
         const f16* __restrict__ B, int ldb, long sBo, long sBi,
         const float* __restrict__ bias, long sBias, int nB,
         float* __restrict__ C, f16* __restrict__ Chi,
         int ldc, long sC, int K, float alpha, int relu,
         int kSplit, f16* __restrict__ Cpart)
{
    constexpr int MW = MT / 64;
    constexpr int NW = 8 / MW;
    constexpr int WN = 128 / NW;
    constexpr int NT = WN / 8;
    constexpr uint32_t ABYTES = MT * 128;
    constexpr uint32_t STG = ABYTES + 16384;
    constexpr int AUNITS = MT * 8;
    constexpr int UNITS = AUNITS + 1024;

    extern __shared__ char sm[];
    const uint32_t sb = s2u(sm);
    const int tid = threadIdx.x;
    const int wid = tid >> 5;
    const int lane = tid & 31;
    const int wm = wid / NW;
    const int wn = wid % NW;
    int zb = blockIdx.z;
    int zs = 0;
    if (kSplit > 1) { zs = zb % kSplit; zb /= kSplit; }
    const int zo = zb / nB;
    const int zi = zb - zo * nB;
    const long row0 = (long)blockIdx.y * MT;
    const long col0 = (long)blockIdx.x * 128;

    const int Ksub = K / kSplit;
    const long koff = (long)zs * Ksub;

    A += zo * sAo + zi * sAi + koff;
    B += zo * sBo + zi * sBi + koff;

    const int nch = Ksub >> 6;

    auto load_chunk = [&](int ch, int stage) {
        const long k0 = (long)ch << 6;
#pragma unroll
        for (int i = 0; i < UNITS / 256; i++) {
            const int u = tid + (i << 8);
            const f16* p;
            uint32_t base;
            int q;
            if (u < AUNITS) {
                q = u;
                p = A + (row0 + (q >> 3)) * lda;
                base = 0;
            } else {
                q = u - AUNITS;
                p = B + (col0 + (q >> 3)) * ldb;
                base = ABYTES;
            }
            const int sg = (q & 7) << 3;
            uint32_t off = (uint32_t)(q << 4);
            off ^= (off >> 3) & 0x70;
            cp16(sb + (uint32_t)stage * STG + base + off, p + k0 + sg);
        }
        CP_COMMIT();
    };

    float acc[4][NT][4];
#pragma unroll
    for (int a = 0; a < 4; a++)
#pragma unroll
        for (int b = 0; b < NT; b++)
#pragma unroll
            for (int c = 0; c < 4; c++) acc[a][b][c] = 0.0f;

    load_chunk(0, 0);
    load_chunk(1, 1);

    for (int ch = 0; ch < nch; ch++) {
        if (ch + 2 < nch) {
            load_chunk(ch + 2, (ch + 2) % 3);
            CP_WAIT(2);
        } else {
            CP_WAIT(0);
        }
        __syncthreads();

        const uint32_t stg = sb + (uint32_t)(ch % 3) * STG;

#pragma unroll
        for (int ks = 0; ks < 4; ks++) {
            uint32_t ah[4][4], bh[NT / 2][4];
#pragma unroll
            for (int mt = 0; mt < 4; mt++) {
                const int row = wm * 64 + mt * 16 + (lane & 15);
                const int colb = ks * 32 + ((lane >> 4) << 4);
                uint32_t off = (uint32_t)(row * 128 + colb);
                off ^= (off >> 3) & 0x70;
                ldm_x4(ah[mt], stg + off);
            }
#pragma unroll
            for (int nb = 0; nb < NT / 2; nb++) {
                const int row = wn * WN + nb * 16 + (lane & 7) + ((lane >> 4) << 3);
                const int colb = ks * 32 + (((lane >> 3) & 1) << 4);
                uint32_t off = (uint32_t)(row * 128 + colb);
                off ^= (off >> 3) & 0x70;
                ldm_x4(bh[nb], stg + ABYTES + off);
            }
#pragma unroll
            for (int mt = 0; mt < 4; mt++)
#pragma unroll
                for (int nt = 0; nt < NT; nt++) {
                    const uint32_t* bhp = &bh[nt >> 1][(nt & 1) * 2];
                    mma_f16(acc[mt][nt], ah[mt], bhp);
                }
        }
        __syncthreads();
    }

    // -------- epilogue --------
    if (kSplit > 1) {
        const long Npart = (long)gridDim.x * 128;
        const long Mtot = (long)gridDim.y * MT;
        const int nzb = gridDim.z / kSplit;
        f16* dst = Cpart + ((long)zs * nzb + zb) * Mtot * Npart;
#pragma unroll
        for (int mt = 0; mt < 4; mt++)
#pragma unroll
            for (int nt = 0; nt < NT; nt++) {
                float* d = acc[mt][nt];
                const long gm = row0 + wm * 64 + mt * 16 + (lane >> 2);
                const long gn = col0 + wn * WN + nt * 8 + (lane & 3) * 2;
#pragma unroll
                for (int half = 0; half < 2; half++) {
                    const long r = gm + half * 8;
                    *(uint32_t*)(dst + r * Npart + gn) =
                        pack2(d[half * 2 + 0] * alpha, d[half * 2 + 1] * alpha);
                }
            }
        return;
    }

    float* Cz = C ? C + sC * zb : nullptr;
    f16* Hz = Chi ? Chi + sC * zb : nullptr;
    const float* bz = bias ? bias + (long)zb * sBias : nullptr;

#pragma unroll
    for (int mt = 0; mt < 4; mt++)
#pragma unroll
        for (int nt = 0; nt < NT; nt++) {
            float* d = acc[mt][nt];
            const long gm = row0 + wm * 64 + mt * 16 + (lane >> 2);
            const long gn = col0 + wn * WN + nt * 8 + (lane & 3) * 2;
            float b0 = 0.0f, b1 = 0.0f;
            if (bz) { b0 = __ldg(bz + gn); b1 = __ldg(bz + gn + 1); }
#pragma unroll
            for (int half = 0; half < 2; half++) {
                const long r = gm + half * 8;
                float x0 = d[half * 2 + 0] * alpha + b0;
                float x1 = d[half * 2 + 1] * alpha + b1;
                if (relu) { x0 = fmaxf(x0, 0.0f); x1 = fmaxf(x1, 0.0f); }
                const long o = r * ldc + gn;
                if (Cz) *(float2*)(Cz + o) = make_float2(x0, x1);
                if (Hz) *(uint32_t*)(Hz + o) = pack2(x0, x1);
            }
        }
}

// =============== split-K combine: out = sum_s p_s (+bias, relu) -> f16 =========
__global__ void __launch_bounds__(256)
combine_k(const f16* __restrict__ part, long perMat, long total, int Npart,
          int kSplit, const float* __restrict__ bias, int relu,
          f16* __restrict__ outH, int ldc, long sC)
{
    const long i = ((long)blockIdx.x * blockDim.x + threadIdx.x) * 4;
    if (i >= total) return;
    const long zb = i / perMat;
    const long rem = i - zb * perMat;
    const long m = rem / Npart;
    const int n = (int)(rem - m * Npart);
    float x0 = 0.0f, x1 = 0.0f, x2 = 0.0f, x3 = 0.0f;
    for (int s = 0; s < kSplit; s++) {
        const uint2 pv = *(const uint2*)(part + (long)s * total + i);
        float2 a = __half22float2(*(const __half2*)&pv.x);
        float2 b = __half22float2(*(const __half2*)&pv.y);
        x0 += a.x; x1 += a.y; x2 += b.x; x3 += b.y;
    }
    if (bias) {
        x0 += __ldg(bias + n); x1 += __ldg(bias + n + 1);
        x2 += __ldg(bias + n + 2); x3 += __ldg(bias + n + 3);
    }
    if (relu) {
        x0 = fmaxf(x0, 0.0f); x1 = fmaxf(x1, 0.0f);
        x2 = fmaxf(x2, 0.0f); x3 = fmaxf(x3, 0.0f);
    }
    const long o = zb * sC + m * ldc + n;
    uint2 wh;
    wh.x = pack2(x0, x1);
    wh.y = pack2(x2, x3);
    *(uint2*)(outH + o) = wh;
}

// ====== fused: h = LayerNorm(h + (sum_s p_s + bias)) * g + b, f32 + f16 ========
// Vectorized: thread t owns cols [4t, 4t+4). partials via uint2 (4xf16),
// h/bias/g/b via float4.
__global__ void __launch_bounds__(256)
add_ln_combine(float* __restrict__ h, const f16* __restrict__ part, int kSplit,
               const float* __restrict__ bias,
               const float* __restrict__ g, const float* __restrict__ b,
               f16* __restrict__ ohi)
{
    const long row = blockIdx.x;
    float* hp = h + row * (long)DIM;
    const int tid = threadIdx.x;
    const int c4 = tid * 4;

    float4 hv = *(float4*)(hp + c4);
    float4 bi = *(const float4*)(bias + c4);
    float v0 = bi.x, v1 = bi.y, v2 = bi.z, v3 = bi.w;
    for (int s = 0; s < kSplit; s++) {
        const uint2 pv = *(const uint2*)(part + (long)s * SEQ * DIM + row * (long)DIM + c4);
        float2 a = __half22float2(*(const __half2*)&pv.x);
        float2 c = __half22float2(*(const __half2*)&pv.y);
        v0 += a.x; v1 += a.y; v2 += c.x; v3 += c.y;
    }
    v0 += hv.x; v1 += hv.y; v2 += hv.z; v3 += hv.w;

    __shared__ float red[256];
    red[tid] = v0 + v1 + v2 + v3;
    __syncthreads();
    for (int s = 128; s > 0; s >>= 1) {
        if (tid < s) red[tid] += red[tid + s];
        __syncthreads();
    }
    const float mu = red[0] * (1.0f / DIM);
    __syncthreads();

    const float d0 = v0 - mu, d1 = v1 - mu, d2 = v2 - mu, d3 = v3 - mu;
    red[tid] = d0 * d0 + d1 * d1 + d2 * d2 + d3 * d3;
    __syncthreads();
    for (int s = 128; s > 0; s >>= 1) {
        if (tid < s) red[tid] += red[tid + s];
        __syncthreads();
    }
    const float inv = rsqrtf(red[0] * (1.0f / DIM) + LN_EPS);
    __syncthreads();

    const float4 gv = *(const float4*)(g + c4);
    const float4 bv = *(const float4*)(b + c4);
    float y0 = gv.x * d0 * inv + bv.x;
    float y1 = gv.y * d1 * inv + bv.y;
    float y2 = gv.z * d2 * inv + bv.z;
    float y3 = gv.w * d3 * inv + bv.w;
    *(float4*)(hp + c4) = make_float4(y0, y1, y2, y3);
    uint2 wh;
    wh.x = pack2(y0, y1);
    wh.y = pack2(y2, y3);
    *(uint2*)(ohi + row * (long)DIM + c4) = wh;
}

// ============= transpose f32 -> f16 (hi only): [R][C] -> [C][R] ================
__global__ void __launch_bounds__(256)
transpose_f32_f16(const float* __restrict__ in, f16* __restrict__ ohi,
                  int R, int Ccols, long sIn, long sOut)
{
    __shared__ float t[32][33];
    const float* ip = in + sIn * blockIdx.z;
    const int c0 = blockIdx.x * 32, r0 = blockIdx.y * 32;
    const int tx = threadIdx.x & 31, ty = threadIdx.x >> 5;
#pragma unroll
    for (int j = 0; j < 32; j += 8)
        t[ty + j][tx] = ip[(long)(r0 + ty + j) * Ccols + c0 + tx];
    __syncthreads();
#pragma unroll
    for (int j = 0; j < 32; j += 8) {
        long o = sOut * blockIdx.z + (long)(c0 + ty + j) * R + r0 + tx;
        ohi[o] = __float2half_rn(t[tx][ty + j]);
    }
}

// ============= transpose f32 -> f16 hi/lo: [R][C] -> [C][R] (for Wh) ===========
__global__ void __launch_bounds__(256)
transpose_split(const float* __restrict__ in, f16* __restrict__ ohi, f16* __restrict__ olo,
                int R, int Ccols, long sIn, long sOut)
{
    __shared__ float t[32][33];
    const float* ip = in + sIn * blockIdx.z;
    const int c0 = blockIdx.x * 32, r0 = blockIdx.y * 32;
    const int tx = threadIdx.x & 31, ty = threadIdx.x >> 5;
#pragma unroll
    for (int j = 0; j < 32; j += 8)
        t[ty + j][tx] = ip[(long)(r0 + ty + j) * Ccols + c0 + tx];
    __syncthreads();
#pragma unroll
    for (int j = 0; j < 32; j += 8) {
        float x = t[tx][ty + j];
        f16 h, l; split2(x, h, l);
        long o = sOut * blockIdx.z + (long)(c0 + ty + j) * R + r0 + tx;
        ohi[o] = h; olo[o] = l;
    }
}

// ========== plain f16 cast of Wq|Wk|Wv into [qkv][l][in][out] =================
__global__ void __launch_bounds__(256)
split_plain_qkv(const float* __restrict__ Wq, const float* __restrict__ Wk,
                const float* __restrict__ Wv, f16* __restrict__ ohi)
{
    const long DDL = (long)NLAYER * DIM * DIM;
    const long idx = (long)blockIdx.x * blockDim.x + threadIdx.x;
    if (idx >= 3 * DDL) return;
    const int w = (int)(idx / DDL);
    const long r = idx - (long)w * DDL;
    const float* src = (w == 0) ? Wq : (w == 1) ? Wk : Wv;
    ohi[idx] = __float2half_rn(src[r]);
}

// ================ f16 transpose: [R][C] -> [C][R] ==============================
__global__ void __launch_bounds__(256)
transpose_hi(const f16* __restrict__ ihi, f16* __restrict__ ohi,
             int R, int Ccols, long sIn, long sOut)
{
    __shared__ unsigned short t[32][33];
    const int c0 = blockIdx.x * 32, r0 = blockIdx.y * 32;
    const int tx = threadIdx.x & 31, ty = threadIdx.x >> 5;
    const f16* a = ihi + sIn * blockIdx.z;
    f16* o = ohi + sOut * blockIdx.z;
#pragma unroll
    for (int j = 0; j < 32; j += 8)
        t[ty + j][tx] = __half_as_ushort(a[(long)(r0 + ty + j) * Ccols + c0 + tx]);
    __syncthreads();
#pragma unroll
    for (int j = 0; j < 32; j += 8)
        o[(long)(c0 + ty + j) * R + r0 + tx] = __ushort_as_half(t[tx][ty + j]);
}

// ============= fused head bias: b'[l][qkv][a][e] = b_qkv . Wh[l][a][:,e] + bh ==
__global__ void __launch_bounds__(256)
bias_head_kernel(const float* __restrict__ bq, const float* __restrict__ bk,
                 const float* __restrict__ bv, const float* __restrict__ bh,
                 const f16* __restrict__ wht_hi, const f16* __restrict__ wht_lo,
                 float* __restrict__ out)
{
    const int warpId = (blockIdx.x * blockDim.x + threadIdx.x) >> 5;
    const int lane = threadIdx.x & 31;
    const int total = NLAYER * 3 * NHEAD * DHEAD;
    if (warpId >= total) return;
    const int e = warpId & (DHEAD - 1);
    const int a = (warpId / DHEAD) & (NHEAD - 1);
    const int qkv = (warpId / (DHEAD * NHEAD)) % 3;
    const int l = warpId / (DHEAD * NHEAD * 3);
    const float* bsrc = ((qkv == 0) ? bq : (qkv == 1) ? bk : bv) + (long)l * DIM;
    const long wrow = (((long)l * NHEAD + a) * DHEAD + e) * DIM;
    float s = 0.0f;
    for (int i = lane; i < DIM; i += 32)
        s += bsrc[i] * (__half2float(wht_hi[wrow + i]) + __half2float(wht_lo[wrow + i]));
#pragma unroll
    for (int off = 16; off > 0; off >>= 1) s += __shfl_down_sync(0xFFFFFFFFu, s, off);
    if (lane == 0) out[warpId] = s + bh[((long)l * NHEAD + a) * DHEAD + e];
}

// ======== fused prologue misc: copy + f16 cast of hidden =======================
__global__ void __launch_bounds__(256)
prep_misc(const float* __restrict__ hidden, float* __restrict__ h,
          f16* __restrict__ dhi)
{
    const int idx = blockIdx.x * blockDim.x + threadIdx.x;
    if (idx < SEQ * DIM) {
        float v = hidden[idx];
        h[idx] = v;
        dhi[idx] = __float2half_rn(v);
    }
}

// ============ softmax over rows (half2-vectorized, in-place) ===================
__global__ void __launch_bounds__(256)
softmax_kernel(f16* __restrict__ s16)
{
    const size_t base = (size_t)blockIdx.x * SEQ;
    __half2* p = (__half2*)(s16 + base);      // 1536 half2 per row
    const int tid = threadIdx.x;

    float2 v[6];
    float mx = -1e30f;
#pragma unroll
    for (int i = 0; i < 6; i++) {
        v[i] = __half22float2(p[tid + i * 256]);
        mx = fmaxf(mx, fmaxf(v[i].x, v[i].y));
    }
    __shared__ float red[256];
    red[tid] = mx;
    __syncthreads();
    for (int s = 128; s > 0; s >>= 1) {
        if (tid < s) red[tid] = fmaxf(red[tid], red[tid + s]);
        __syncthreads();
    }
    mx = red[0];
    __syncthreads();

    float sum = 0.0f;
#pragma unroll
    for (int i = 0; i < 6; i++) {
        v[i].x = __expf(v[i].x - mx);
        v[i].y = __expf(v[i].y - mx);
        sum += v[i].x + v[i].y;
    }
    red[tid] = sum;
    __syncthreads();
    for (int s = 128; s > 0; s >>= 1) {
        if (tid < s) red[tid] += red[tid + s];
        __syncthreads();
    }
    const float inv = 1.0f / red[0];
#pragma unroll
    for (int i = 0; i < 6; i++)
        p[tid + i * 256] = __floats2half2_rn(v[i].x * inv, v[i].y * inv);
}

// ======================= output heads =======================
__global__ void __launch_bounds__(256)
heads_kernel(const float* __restrict__ h, const float* __restrict__ Whead,
             const float* __restrict__ bhead, const int* __restrict__ nev,
             const int* __restrict__ nag, float* __restrict__ out, int total)
{
    const int warpId = (blockIdx.x * blockDim.x + threadIdx.x) >> 5;
    const int lane = threadIdx.x & 31;
    if (warpId >= total) return;
    const int NEv = *nev;
    const int NAg = *nag;
    int headIdx, token;
    if (warpId < 3 * NAg) {
        headIdx = warpId / NAg;
        token = NEv + warpId % NAg;
    } else {
        headIdx = 3;
        token = warpId - 3 * NAg;
    }
    const float* hr = h + (long)token * DIM;
    const float* w = Whead + (long)headIdx * DIM;
    float s = 0.0f;
    for (int i = lane; i < DIM; i += 32) s = fmaf(hr[i], w[i], s);
#pragma unroll
    for (int off = 16; off > 0; off >>= 1) s += __shfl_down_sync(0xFFFFFFFFu, s, off);
    if (lane == 0) out[warpId] = s + bhead[headIdx];
}

// ======================= host orchestration =======================
#define SMEM128 (3 * (128 * 128 + 16384))
#define SMEM256 (3 * (256 * 128 + 16384))

template <int MT>
static void tcg(const f16* A, int lda, long sAo, long sAi,
                const f16* B, int ldb, long sBo, long sBi,
                const float* bias, long sBias, int nB,
                float* C, f16* Chi, int ldc, long sC,
                int M, int N, int K, int batch, float alpha, int relu,
                int kSplit = 1, f16* Cpart = nullptr)
{
    dim3 grid(N / 128, M / MT, batch * kSplit);
    const int smem = (MT == 128) ? SMEM128 : SMEM256;
    mma_gemm<MT><<<grid, 256, smem>>>(A, lda, sAo, sAi, B, ldb, sBo, sBi,
                                      bias, sBias, nB, C, Chi, ldc, sC, K, alpha, relu,
                                      kSplit, Cpart);
}

#define SYM(var, name) cudaGetSymbolAddress((void**)&var, name)

extern "C" void kernel_launch(void* const* d_in, const int* in_sizes, int n_in,
                              void* d_out, int out_size)
{
    const float* hidden = (const float*)d_in[0];
    const float* Wq = (const float*)d_in[1];
    const float* bq = (const float*)d_in[2];
    const float* Wk = (const float*)d_in[3];
    const float* bk = (const float*)d_in[4];
    const float* Wv = (const float*)d_in[5];
    const float* bv = (const float*)d_in[6];
    const float* Wh = (const float*)d_in[7];
    const float* bh = (const float*)d_in[8];
    const float* Wo = (const float*)d_in[9];
    const float* bo = (const float*)d_in[10];
    const float* g1 = (const float*)d_in[11];
    const float* b1n = (const float*)d_in[12];
    const float* g2 = (const float*)d_in[13];
    const float* b2n = (const float*)d_in[14];
    const float* Wf1 = (const float*)d_in[15];
    const float* bf1 = (const float*)d_in[16];
    const float* Wf2 = (const float*)d_in[17];
    const float* bf2 = (const float*)d_in[18];
    const float* Whead = (const float*)d_in[19];
    const float* bhead = (const float*)d_in[20];
    const int* n_events = (const int*)d_in[21];
    const int* n_agents = (const int*)d_in[22];
    (void)in_sizes; (void)n_in;

    cudaFuncSetAttribute(mma_gemm<128>, cudaFuncAttributeMaxDynamicSharedMemorySize, SMEM128);
    cudaFuncSetAttribute(mma_gemm<256>, cudaFuncAttributeMaxDynamicSharedMemorySize, SMEM256);

    float *h, *bprime;
    f16 *spl;
    SYM(h, g_h); SYM(bprime, g_bprime); SYM(spl, g_split);
    f16 *h_hi, *qkvh, *vht, *ctx, *f1, *at;
    SYM(h_hi, g_h_hi); SYM(qkvh, g_qkvh); SYM(vht, g_vht);
    SYM(ctx, g_ctx); SYM(f1, g_f1); SYM(at, g_at);
    f16 *wsplit, *wpt, *wot, *wht_hi, *wht_lo, *w1t, *w2t;
    SYM(wsplit, g_wsplit); SYM(wpt, g_wpt); SYM(wot, g_wot);
    SYM(wht_hi, g_wht_hi); SYM(wht_lo, g_wht_lo);
    SYM(w1t, g_w1t); SYM(w2t, g_w2t);

    const long DD = (long)DIM * DIM;
    const long SD = (long)SEQ * DIM;
    const long SS = (long)SEQ * SEQ;
    const long SDh = (long)SEQ * DHEAD;
    const long WHL = (long)NHEAD * DHEAD * DIM;
    const long HD = (long)DHEAD * DIM;

    // ---- prologue (ordered so launch #5 is a GEMM for ncu -s 5 -c 1) ----
    // [0] Wh transpose+split
    transpose_split<<<dim3(DHEAD / 32, DIM / 32, NLAYER * NHEAD), 256>>>(
        Wh, wht_hi, wht_lo, DIM, DHEAD, HD, HD);
    // [1] Wq/Wk/Wv f16 cast
    {
        const long totalW = 3 * (long)NLAYER * DD;
        split_plain_qkv<<<(int)((totalW + 255) / 256), 256>>>(Wq, Wk, Wv, wsplit);
    }
    // [2] hidden copy+cast
    prep_misc<<<(SEQ * DIM + 255) / 256, 256>>>(hidden, h, h_hi);
    // [3] fused head bias
    {
        const int totalB = NLAYER * 3 * NHEAD * DHEAD;
        bias_head_kernel<<<(totalB * 32 + 255) / 256, 256>>>(bq, bk, bv, bh, wht_hi, wht_lo, bprime);
    }
    // [4..6] W'^T precompute GEMMs  (#5 = qkv=1 launch -> ncu profiles mma_gemm<128>)
    for (int qkv = 0; qkv < 3; qkv++) {
        tcg<128>(wht_hi, DIM, WHL, HD,
                 wsplit + (long)qkv * NLAYER * DD, DIM, DD, 0,
                 nullptr, 0, NHEAD,
                 nullptr, wpt + (long)qkv * NLAYER * WHL,
                 DIM, HD, DHEAD, DIM, DIM, NLAYER * NHEAD, 1.0f, 0);
    }
    // [7..9] remaining weight transposes (needed from layer 0's Wo/FFN stages)
    transpose_f32_f16<<<dim3(DIM / 32, DIM / 32, NLAYER), 256>>>(Wo, wot, DIM, DIM, DD, DD);
    transpose_f32_f16<<<dim3(2 * DIM / 32, DIM / 32, NLAYER), 256>>>(Wf1, w1t, DIM, 2 * DIM, 2 * DD, 2 * DD);
    transpose_f32_f16<<<dim3(DIM / 32, 2 * DIM / 32, NLAYER), 256>>>(Wf2, w2t, 2 * DIM, DIM, 2 * DD, 2 * DD);

    const float attn_scale = 1.0f / 16.0f;

    for (int l = 0; l < NLAYER; l++) {
        // fused QKV+head projections: qkvh[qkv][a] = h @ W'[l][qkv][a] + b'
        tcg<256>(h_hi, DIM, 0, 0,
                 wpt + l * WHL, DIM, (long)NLAYER * WHL, HD,
                 bprime + (long)l * 3 * NHEAD * DHEAD, DHEAD, NHEAD,
                 nullptr, qkvh, DHEAD, SDh, SEQ, DHEAD, DIM, 3 * NHEAD, 1.0f, 0);
        // Vh [head][t][e] -> [head][e][t]
        transpose_hi<<<dim3(DHEAD / 32, SEQ / 32, NHEAD), 256>>>(
            qkvh + 2 * SD, vht, SEQ, DHEAD, SDh, SDh);
        // scores = scale * Qh @ Kh^T -> f16
        tcg<256>(qkvh, DHEAD, SDh, 0,
                 qkvh + SD, DHEAD, SDh, 0,
                 nullptr, 0, 1,
                 nullptr, at, SEQ, SS, SEQ, SEQ, DHEAD, NHEAD, attn_scale, 0);
        // softmax in-place
        softmax_kernel<<<NHEAD * SEQ, 256>>>(at);
        // ctx = attn @ Vh  (split-K=3 -> combine to f16 [t][a*DHEAD+e])
        tcg<256>(at, SEQ, SS, 0,
                 vht, SEQ, SDh, 0,
                 nullptr, 0, 1,
                 nullptr, nullptr, 0, 0, SEQ, DHEAD, SEQ, NHEAD, 1.0f, 0,
                 3, spl);
        {
            const long total = (long)NHEAD * SEQ * DHEAD;
            combine_k<<<(int)((total / 4 + 255) / 256), 256>>>(
                spl, SDh, total, DHEAD, 3, nullptr, 0, ctx, DIM, DHEAD);
        }
        // attn_out partials = ctx @ Wo (split-K=4), fused combine+bias+LN
        tcg<256>(ctx, DIM, 0, 0,
                 wot + l * DD, DIM, 0, 0,
                 nullptr, 0, 1,
                 nullptr, nullptr, 0, 0, SEQ, DIM, DIM, 1, 1.0f, 0,
                 4, spl);
        add_ln_combine<<<SEQ, 256>>>(h, spl, 4, bo + (long)l * DIM,
                                     g1 + (long)l * DIM, b1n + (long)l * DIM, h_hi);
        // FFN1: split-K=2, combine does bias+relu -> f16
        tcg<256>(h_hi, DIM, 0, 0,
                 w1t + l * 2 * DD, DIM, 0, 0,
                 nullptr, 0, 1,
                 nullptr, nullptr, 0, 0, SEQ, 2 * DIM, DIM, 1, 1.0f, 0,
                 2, spl);
        combine_k<<<(int)((2 * SD / 4 + 255) / 256), 256>>>(
            spl, 2 * SD, 2 * SD, 2 * DIM, 2, bf1 + (long)l * 2 * DIM, 1, f1, 2 * DIM, 0);
        // FFN2: split-K=4, fused combine+bias+LN
        tcg<256>(f1, 2 * DIM, 0, 0,
                 w2t + l * 2 * DD, 2 * DIM, 0, 0,
                 nullptr, 0, 1,
                 nullptr, nullptr, 0, 0, SEQ, DIM, 2 * DIM, 1, 1.0f, 0,
                 4, spl);
        add_ln_combine<<<SEQ, 256>>>(h, spl, 4, bf2 + (long)l * DIM,
                                     g2 + (long)l * DIM, b2n + (long)l * DIM, h_hi);
    }

    const int blocks = (out_size * 32 + 255) / 256;
    heads_kernel<<<blocks, 256>>>(h, Whead, bhead, n_events, n_agents, (float*)d_out, out_size);
}